// round 9
// baseline (speedup 1.0000x reference)
#include <cuda_runtime.h>
#include <cuda_bf16.h>
#include <cuda_fp16.h>
#include <math.h>
#include <cstdint>

#define B_ 2
#define S_ 2048
#define D_ 4096
#define H_ 32
#define KV_ 8
#define HD_ 128
#define T_ (B_*S_)
#define REP_ (H_/KV_)

// ---------------------------------------------------------------------------
// Scratch (device globals: allocation-free rule)
// ---------------------------------------------------------------------------
__device__ float g_q[T_ * D_];
__device__ float g_k[T_ * KV_ * HD_];
__device__ float g_v[T_ * KV_ * HD_];
__device__ float g_attn[T_ * D_];

__device__ float g_xt[T_ * D_];
__device__ float g_wqt[D_ * D_];
__device__ float g_wkt[KV_ * HD_ * D_];
__device__ float g_wvt[KV_ * HD_ * D_];
__device__ float g_wot[D_ * D_];

__device__ float g_qt[T_ * D_];            // roped + scale*log2e + rna Q
__device__ float g_kt[T_ * KV_ * HD_];     // roped + rna K
__device__ __half g_vh[T_ * KV_ * HD_];
__device__ __half g_vl[T_ * KV_ * HD_];

// ---------------------------------------------------------------------------
// Helpers
// ---------------------------------------------------------------------------
__device__ __forceinline__ uint32_t smem_to_u32(const void* smem_ptr) {
    uint32_t addr;
    asm("{ .reg .u64 tmp; cvta.to.shared.u64 tmp, %1; cvt.u32.u64 %0, tmp; }"
        : "=r"(addr) : "l"(smem_ptr));
    return addr;
}
__device__ __forceinline__ void cp_async16(uint32_t saddr, const void* gaddr) {
    asm volatile("cp.async.cg.shared.global [%0], [%1], 16;"
                 :: "r"(saddr), "l"(gaddr));
}
#define CP_COMMIT() asm volatile("cp.async.commit_group;")
#define CP_WAIT(n)  asm volatile("cp.async.wait_group %0;" :: "n"(n))

__device__ __forceinline__ uint32_t lds32(uint32_t addr) {
    uint32_t v;
    asm("ld.shared.b32 %0, [%1];" : "=r"(v) : "r"(addr));
    return v;
}
__device__ __forceinline__ float ex2(float x) {
    float r;
    asm("ex2.approx.f32 %0, %1;" : "=f"(r) : "f"(x));
    return r;
}

#define MMA_TF32(d, a, b) \
    asm volatile("mma.sync.aligned.m16n8k8.row.col.f32.tf32.tf32.f32 " \
        "{%0,%1,%2,%3}, {%4,%5,%6,%7}, {%8,%9}, {%0,%1,%2,%3};" \
        : "+f"((d)[0]), "+f"((d)[1]), "+f"((d)[2]), "+f"((d)[3]) \
        : "r"((a)[0]), "r"((a)[1]), "r"((a)[2]), "r"((a)[3]), \
          "r"((b)[0]), "r"((b)[1]))

#define MMA_TF32_2(d, a0, a1, a2, a3, bb0, bb1) \
    asm volatile("mma.sync.aligned.m16n8k8.row.col.f32.tf32.tf32.f32 " \
        "{%0,%1,%2,%3}, {%4,%5,%6,%7}, {%8,%9}, {%0,%1,%2,%3};" \
        : "+f"((d)[0]), "+f"((d)[1]), "+f"((d)[2]), "+f"((d)[3]) \
        : "r"(a0), "r"(a1), "r"(a2), "r"(a3), "r"(bb0), "r"(bb1))

#define MMA_F16(d, a, bb0, bb1) \
    asm volatile("mma.sync.aligned.m16n8k16.row.col.f32.f16.f16.f32 " \
        "{%0,%1,%2,%3}, {%4,%5,%6,%7}, {%8,%9}, {%0,%1,%2,%3};" \
        : "+f"((d)[0]), "+f"((d)[1]), "+f"((d)[2]), "+f"((d)[3]) \
        : "r"((a)[0]), "r"((a)[1]), "r"((a)[2]), "r"((a)[3]), \
          "r"(bb0), "r"(bb1))

#define LDSM4(d0,d1,d2,d3,a) \
    asm volatile("ldmatrix.sync.aligned.m8n8.x4.shared.b16 {%0,%1,%2,%3}, [%4];" \
        : "=r"(d0), "=r"(d1), "=r"(d2), "=r"(d3) : "r"(a))
#define LDSM4T(d0,d1,d2,d3,a) \
    asm volatile("ldmatrix.sync.aligned.m8n8.x4.trans.shared.b16 {%0,%1,%2,%3}, [%4];" \
        : "=r"(d0), "=r"(d1), "=r"(d2), "=r"(d3) : "r"(a))

__device__ __forceinline__ uint32_t packf16(float lo, float hi) {
    uint32_t r;
    asm("cvt.rn.f16x2.f32 %0, %1, %2;" : "=r"(r) : "f"(hi), "f"(lo));
    return r;
}
__device__ __forceinline__ float f16_round(float x) {
    return __half2float(__float2half(x));
}
__device__ __forceinline__ uint32_t tf32_rna(float x) {
    uint32_t r;
    asm("cvt.rna.tf32.f32 %0, %1;" : "=r"(r) : "f"(x));
    return r;
}

// ---------------------------------------------------------------------------
// fp32 -> tf32 rounding
// ---------------------------------------------------------------------------
__global__ void round_tf32(const float* __restrict__ X, float* __restrict__ Y, int n4)
{
    int i = blockIdx.x * blockDim.x + threadIdx.x;
    if (i >= n4) return;
    float4 v = reinterpret_cast<const float4*>(X)[i];
    uint4 o;
    o.x = tf32_rna(v.x); o.y = tf32_rna(v.y);
    o.z = tf32_rna(v.z); o.w = tf32_rna(v.w);
    reinterpret_cast<uint4*>(Y)[i] = o;
}

// ---------------------------------------------------------------------------
// fp32 -> fp16 hi/lo split (V)
// ---------------------------------------------------------------------------
__global__ void split_f16(const float* __restrict__ X,
                          __half* __restrict__ Hh, __half* __restrict__ Ll, int n4)
{
    int i = blockIdx.x * blockDim.x + threadIdx.x;
    if (i >= n4) return;
    float4 v = reinterpret_cast<const float4*>(X)[i];
    __half h0 = __float2half(v.x), h1 = __float2half(v.y);
    __half h2 = __float2half(v.z), h3 = __float2half(v.w);
    __half l0 = __float2half(v.x - __half2float(h0));
    __half l1 = __float2half(v.y - __half2float(h1));
    __half l2 = __float2half(v.z - __half2float(h2));
    __half l3 = __float2half(v.w - __half2float(h3));
    ushort4 hp, lp;
    hp.x = __half_as_ushort(h0); hp.y = __half_as_ushort(h1);
    hp.z = __half_as_ushort(h2); hp.w = __half_as_ushort(h3);
    lp.x = __half_as_ushort(l0); lp.y = __half_as_ushort(l1);
    lp.z = __half_as_ushort(l2); lp.w = __half_as_ushort(l3);
    reinterpret_cast<ushort4*>(Hh)[i] = hp;
    reinterpret_cast<ushort4*>(Ll)[i] = lp;
}

// ---------------------------------------------------------------------------
// Fused RoPE (+scale) + tf32 rounding
// ---------------------------------------------------------------------------
__global__ void rope_tf32(const float* __restrict__ src, float* __restrict__ dst,
                          const float* __restrict__ fc, const float* __restrict__ fs,
                          int heads, float sc)
{
    int idx = blockIdx.x * blockDim.x + threadIdx.x;
    int total = T_ * heads * (HD_/4);
    if (idx >= total) return;
    int i32 = idx & 31;
    int rem = idx >> 5;
    int h   = rem % heads;
    int t   = rem / heads;
    int s   = t & (S_ - 1);
    int p0  = 2 * i32;
    float c0 = fc[s*64 + p0],     s0 = fs[s*64 + p0];
    float c1 = fc[s*64 + p0 + 1], s1 = fs[s*64 + p0 + 1];
    size_t base = (size_t)t * heads * HD_ + h * HD_ + 4*i32;
    float4 v = *reinterpret_cast<const float4*>(src + base);
    uint4 o;
    o.x = tf32_rna((v.x * c0 - v.y * s0) * sc);
    o.y = tf32_rna((v.x * s0 + v.y * c0) * sc);
    o.z = tf32_rna((v.z * c1 - v.w * s1) * sc);
    o.w = tf32_rna((v.z * s1 + v.w * c1) * sc);
    *reinterpret_cast<uint4*>(dst + base) = o;
}

// ---------------------------------------------------------------------------
// tf32 GEMM (R5 body, measured fastest) + blockIdx.z weight/output select
// CTA 128x128, BK=64 floats, 3-stage cp.async, scalar-lds fragments.
// ---------------------------------------------------------------------------
#define AT_BYTES (128 * 256)
#define STG_BYTES (2 * AT_BYTES)
#define G3_SMEM (3 * STG_BYTES)

__device__ __forceinline__ void gemm_stage_copy(
    uint32_t sbase, const float* __restrict__ A128, const float* __restrict__ B128,
    int K, int k0, int tid)
{
    #pragma unroll
    for (int t = 0; t < 2; t++) {
        const float* src = t ? B128 : A128;
        #pragma unroll
        for (int it = 0; it < 8; it++) {
            int idx = it * 256 + tid;
            int row = idx >> 4;
            int gr  = idx & 15;
            uint32_t dst = sbase + t * AT_BYTES + row * 256 +
                           (uint32_t)((gr * 16) ^ ((row & 7) << 4));
            cp_async16(dst, src + (size_t)row * K + k0 + gr * 4);
        }
    }
}

__global__ void __launch_bounds__(256, 1)
gemm_tf32(const float* __restrict__ A,
          const float* __restrict__ B0, const float* __restrict__ B1,
          float* __restrict__ C0, float* __restrict__ C1,
          int N, int K)
{
    extern __shared__ __align__(1024) char smem[];
    const uint32_t sb0 = smem_to_u32(smem);
    const int tid  = threadIdx.x;
    const int wid  = tid >> 5;
    const int lane = tid & 31;
    const int bm = blockIdx.y * 128;
    const int bn = blockIdx.x * 128;
    const float* Bw = blockIdx.z ? B1 : B0;
    float* C = blockIdx.z ? C1 : C0;
    const int warp_m = (wid >> 2) * 64;
    const int warp_n = (wid & 3) * 32;
    const int NC = K >> 6;

    const float* A128 = A  + (size_t)bm * K;
    const float* B128 = Bw + (size_t)bn * K;

    float acc[4][4][4];
    #pragma unroll
    for (int i = 0; i < 4; i++)
        #pragma unroll
        for (int j = 0; j < 4; j++)
            #pragma unroll
            for (int r = 0; r < 4; r++) acc[i][j][r] = 0.f;

    const int grp  = lane >> 2;
    const int krem = (lane & 3) * 4;

    gemm_stage_copy(sb0, A128, B128, K, 0, tid);
    CP_COMMIT();
    gemm_stage_copy(sb0 + STG_BYTES, A128, B128, K, 64, tid);
    CP_COMMIT();

    int stage = 0;
    for (int c = 0; c < NC; c++) {
        if (c + 1 < NC) { CP_WAIT(1); } else { CP_WAIT(0); }
        __syncthreads();
        if (c + 2 < NC) {
            int ns = stage + 2; if (ns >= 3) ns -= 3;
            gemm_stage_copy(sb0 + ns * STG_BYTES, A128, B128, K, (c + 2) << 6, tid);
            CP_COMMIT();
        }
        const uint32_t sb = sb0 + stage * STG_BYTES;
        if (++stage == 3) stage = 0;

        #pragma unroll
        for (int ks = 0; ks < 8; ks++) {
            const uint32_t kbyte = ks * 32;
            uint32_t a[4][4], bfr[4][2];
            #pragma unroll
            for (int mt = 0; mt < 4; mt++) {
                int row = warp_m + mt * 16 + grp;
                uint32_t base  = sb + row * 256;
                uint32_t swz   = (uint32_t)((row & 7) << 4);
                a[mt][0] = lds32(base        + ((kbyte + krem)      ^ swz));
                a[mt][1] = lds32(base + 2048 + ((kbyte + krem)      ^ swz));
                a[mt][2] = lds32(base        + ((kbyte + 16 + krem) ^ swz));
                a[mt][3] = lds32(base + 2048 + ((kbyte + 16 + krem) ^ swz));
            }
            #pragma unroll
            for (int nt = 0; nt < 4; nt++) {
                int n = warp_n + nt * 8 + grp;
                uint32_t base = sb + AT_BYTES + n * 256;
                uint32_t swz  = (uint32_t)((n & 7) << 4);
                bfr[nt][0] = lds32(base + ((kbyte + krem)      ^ swz));
                bfr[nt][1] = lds32(base + ((kbyte + 16 + krem) ^ swz));
            }
            #pragma unroll
            for (int mt = 0; mt < 4; mt++)
                #pragma unroll
                for (int nt = 0; nt < 4; nt++)
                    MMA_TF32(acc[mt][nt], a[mt], bfr[nt]);
        }
    }

    #pragma unroll
    for (int mt = 0; mt < 4; mt++) {
        int row = bm + warp_m + mt * 16 + grp;
        #pragma unroll
        for (int nt = 0; nt < 4; nt++) {
            int col = bn + warp_n + nt * 8 + (lane & 3) * 2;
            *(float2*)(C + (size_t)row * N + col) =
                make_float2(acc[mt][nt][0], acc[mt][nt][1]);
            *(float2*)(C + (size_t)(row + 8) * N + col) =
                make_float2(acc[mt][nt][2], acc[mt][nt][3]);
        }
    }
}

// ---------------------------------------------------------------------------
// Flash attention v8: QK^T tf32, PV fp16x3, log2-domain softmax.
// Scores arrive in log2 units (log2e folded into Q prescale): exp -> 1 MUFU.
// l-sum: thread-local with alpha-rescale, warp-reduced once in epilogue.
// ---------------------------------------------------------------------------
#define FQ7 (128 * 512)
#define FK7 (64 * 512)
#define FV7 (64 * 256)
#define FST7 (FK7 + 2 * FV7)
#define FA7_SMEM (FQ7 + 2 * FST7)

__device__ __forceinline__ void fa7_load_kv(
    uint32_t sbase, const float* __restrict__ Kt,
    const __half* __restrict__ Vh, const __half* __restrict__ Vl,
    int tk0, int g, int tid)
{
    const float* ks = Kt + (size_t)tk0 * (KV_*HD_) + g * HD_;
    #pragma unroll
    for (int it = 0; it < 8; it++) {
        int idx = it * 256 + tid;
        int row = idx >> 5, ch = idx & 31;
        uint32_t dst = sbase + row * 512 + (uint32_t)((ch * 16) ^ ((row & 7) << 4));
        cp_async16(dst, ks + (size_t)row * (KV_*HD_) + ch * 4);
    }
    const __half* vs[2] = {Vh + (size_t)tk0 * (KV_*HD_) + g * HD_,
                           Vl + (size_t)tk0 * (KV_*HD_) + g * HD_};
    #pragma unroll
    for (int t = 0; t < 2; t++) {
        #pragma unroll
        for (int it = 0; it < 4; it++) {
            int idx = it * 256 + tid;
            int row = idx >> 4, ch = idx & 15;
            uint32_t dst = sbase + FK7 + t * FV7 + row * 256 +
                           (uint32_t)((ch * 16) ^ ((row & 7) << 4));
            cp_async16(dst, vs[t] + (size_t)row * (KV_*HD_) + ch * 8);
        }
    }
}

__global__ void __launch_bounds__(256, 1)
flash_v8(const float* __restrict__ Qt, const float* __restrict__ Kt,
         const __half* __restrict__ Vh, const __half* __restrict__ Vl,
         float* __restrict__ Og)
{
    extern __shared__ __align__(1024) char fsm[];
    const uint32_t sb = smem_to_u32(fsm);
    const int tid  = threadIdx.x;
    const int wid  = tid >> 5;
    const int lane = tid & 31;
    const int qt = (gridDim.x - 1) - blockIdx.x;
    const int h  = blockIdx.y;
    const int b  = blockIdx.z;
    const int g  = h / REP_;
    const int q0 = qt * 128;
    const int t0 = b * S_ + q0;
    const int nt = 2 * qt + 2;

    const int l7 = lane & 7;
    const int arow = 16 * wid + (lane & 15);
    const uint32_t achk = (lane >= 16) ? 16u : 0u;
    const uint32_t aswz = (uint32_t)((arow & 7) << 4);
    const uint32_t kchk = (uint32_t)((lane >> 3) * 16);
    const uint32_t kswz = (uint32_t)(l7 << 4);
    const int vrow_l = l7 + ((lane >> 3) & 1) * 8;
    const int vgsel  = (lane >= 16) ? 16 : 0;
    const uint32_t vswz = (uint32_t)(l7 << 4);

    fa7_load_kv(sb + FQ7, Kt, Vh, Vl, b * S_, g, tid);
    CP_COMMIT();
    {
        const float* src = Qt + (size_t)t0 * D_ + h * HD_;
        #pragma unroll
        for (int it = 0; it < 16; it++) {
            int idx = it * 256 + tid;
            int row = idx >> 5, ch = idx & 31;
            uint32_t dst = sb + row * 512 + (uint32_t)((ch * 16) ^ ((row & 7) << 4));
            cp_async16(dst, src + (size_t)row * D_ + ch * 4);
        }
        CP_COMMIT();
    }

    float o[16][4];
    #pragma unroll
    for (int f = 0; f < 16; f++)
        #pragma unroll
        for (int r = 0; r < 4; r++) o[f][r] = 0.f;
    float m0 = -1e30f, m1 = -1e30f;
    float lsum0 = 0.f, lsum1 = 0.f;     // thread-local, reduced in epilogue

    const int r0g = q0 + 16 * wid + (lane >> 2);
    const int c0l = (lane & 3) * 2;

    for (int t = 0; t < nt; t++) {
        CP_WAIT(0);
        __syncthreads();
        if (t + 1 < nt) {
            fa7_load_kv(sb + FQ7 + ((t + 1) & 1) * FST7,
                        Kt, Vh, Vl, b * S_ + (t + 1) * 64, g, tid);
            CP_COMMIT();
        }

        const uint32_t kb  = sb + FQ7 + (t & 1) * FST7;
        const uint32_t vhb = kb + FK7;

        float s[8][4];
        #pragma unroll
        for (int j = 0; j < 8; j++)
            #pragma unroll
            for (int r = 0; r < 4; r++) s[j][r] = 0.f;

        // ---- S = Q K^T (tf32; results in log2 units) ----
        #pragma unroll
        for (int dk = 0; dk < 8; dk++) {
            const uint32_t kbyte = (uint32_t)(dk * 64);
            uint32_t qa0[4], qa1[4];
            LDSM4(qa0[0], qa0[1], qa0[2], qa0[3],
                  sb + arow * 512 + ((kbyte + achk) ^ aswz));
            LDSM4(qa1[0], qa1[1], qa1[2], qa1[3],
                  sb + arow * 512 + ((kbyte + 32 + achk) ^ aswz));
            #pragma unroll
            for (int np = 0; np < 8; np++) {
                uint32_t b0, b1, b2, b3;
                LDSM4(b0, b1, b2, b3,
                      kb + (np * 8 + l7) * 512 + ((kbyte + kchk) ^ kswz));
                MMA_TF32_2(s[np], qa0[0], qa0[1], qa0[2], qa0[3], b0, b1);
                MMA_TF32_2(s[np], qa1[0], qa1[1], qa1[2], qa1[3], b2, b3);
            }
        }

        if (t >= 2 * qt) {   // diagonal tile: causal mask
            const int k0 = t * 64;
            #pragma unroll
            for (int j = 0; j < 8; j++) {
                int cg = k0 + 8 * j + c0l;
                if (cg     > r0g)     s[j][0] = -1e30f;
                if (cg + 1 > r0g)     s[j][1] = -1e30f;
                if (cg     > r0g + 8) s[j][2] = -1e30f;
                if (cg + 1 > r0g + 8) s[j][3] = -1e30f;
            }
        }

        // ---- online softmax (log2 domain, MUFU-only exp) ----
        float rm0 = -1e30f, rm1 = -1e30f;
        #pragma unroll
        for (int j = 0; j < 8; j++) {
            rm0 = fmaxf(rm0, fmaxf(s[j][0], s[j][1]));
            rm1 = fmaxf(rm1, fmaxf(s[j][2], s[j][3]));
        }
        rm0 = fmaxf(rm0, __shfl_xor_sync(0xffffffffu, rm0, 1));
        rm0 = fmaxf(rm0, __shfl_xor_sync(0xffffffffu, rm0, 2));
        rm1 = fmaxf(rm1, __shfl_xor_sync(0xffffffffu, rm1, 1));
        rm1 = fmaxf(rm1, __shfl_xor_sync(0xffffffffu, rm1, 2));
        float mn0 = fmaxf(m0, rm0), mn1 = fmaxf(m1, rm1);
        float a0 = ex2(m0 - mn0), a1 = ex2(m1 - mn1);
        m0 = mn0; m1 = mn1;
        float sum0 = 0.f, sum1 = 0.f;
        #pragma unroll
        for (int j = 0; j < 8; j++) {
            s[j][0] = ex2(s[j][0] - mn0);
            s[j][1] = ex2(s[j][1] - mn0);
            s[j][2] = ex2(s[j][2] - mn1);
            s[j][3] = ex2(s[j][3] - mn1);
            sum0 += s[j][0] + s[j][1];
            sum1 += s[j][2] + s[j][3];
        }
        lsum0 = lsum0 * a0 + sum0;
        lsum1 = lsum1 * a1 + sum1;
        #pragma unroll
        for (int f = 0; f < 16; f++) {
            o[f][0] *= a0; o[f][1] *= a0;
            o[f][2] *= a1; o[f][3] *= a1;
        }

        // ---- O += P V (fp16 3-term) ----
        #pragma unroll
        for (int kk = 0; kk < 4; kk++) {
            uint32_t ah[4], al[4];
            float p00 = s[2*kk][0],   p01 = s[2*kk][1];
            float p02 = s[2*kk][2],   p03 = s[2*kk][3];
            float p10 = s[2*kk+1][0], p11 = s[2*kk+1][1];
            float p12 = s[2*kk+1][2], p13 = s[2*kk+1][3];
            ah[0] = packf16(p00, p01);
            ah[1] = packf16(p02, p03);
            ah[2] = packf16(p10, p11);
            ah[3] = packf16(p12, p13);
            al[0] = packf16(p00 - f16_round(p00), p01 - f16_round(p01));
            al[1] = packf16(p02 - f16_round(p02), p03 - f16_round(p03));
            al[2] = packf16(p10 - f16_round(p10), p11 - f16_round(p11));
            al[3] = packf16(p12 - f16_round(p12), p13 - f16_round(p13));
            #pragma unroll
            for (int dgp = 0; dgp < 8; dgp++) {
                uint32_t va = vhb + (kk * 16 + vrow_l) * 256 +
                              (uint32_t)(((dgp * 32) + vgsel) ^ vswz);
                uint32_t b0, b1, b2, b3, c0, c1, c2, c3;
                LDSM4T(b0, b1, b2, b3, va);
                LDSM4T(c0, c1, c2, c3, va + FV7);
                MMA_F16(o[2*dgp],   ah, b0, b1);
                MMA_F16(o[2*dgp],   al, b0, b1);
                MMA_F16(o[2*dgp],   ah, c0, c1);
                MMA_F16(o[2*dgp+1], ah, b2, b3);
                MMA_F16(o[2*dgp+1], al, b2, b3);
                MMA_F16(o[2*dgp+1], ah, c2, c3);
            }
        }
    }

    // epilogue: reduce l once, normalize, tf32-round
    lsum0 += __shfl_xor_sync(0xffffffffu, lsum0, 1);
    lsum0 += __shfl_xor_sync(0xffffffffu, lsum0, 2);
    lsum1 += __shfl_xor_sync(0xffffffffu, lsum1, 1);
    lsum1 += __shfl_xor_sync(0xffffffffu, lsum1, 2);
    const float inv0 = 1.0f / lsum0;
    const float inv1 = 1.0f / lsum1;
    const int rowg = t0 + 16 * wid + (lane >> 2);
    #pragma unroll
    for (int dg = 0; dg < 16; dg++) {
        int col = h * HD_ + dg * 8 + (lane & 3) * 2;
        *(float2*)(Og + (size_t)rowg * D_ + col) = make_float2(
            __uint_as_float(tf32_rna(o[dg][0] * inv0)),
            __uint_as_float(tf32_rna(o[dg][1] * inv0)));
        *(float2*)(Og + (size_t)(rowg + 8) * D_ + col) = make_float2(
            __uint_as_float(tf32_rna(o[dg][2] * inv1)),
            __uint_as_float(tf32_rna(o[dg][3] * inv1)));
    }
}

// ---------------------------------------------------------------------------
extern "C" void kernel_launch(void* const* d_in, const int* in_sizes, int n_in,
                              void* d_out, int out_size)
{
    const float* x  = (const float*)d_in[0];
    const float* fc = (const float*)d_in[1];
    const float* fs = (const float*)d_in[2];
    const float* wq = (const float*)d_in[3];
    const float* wk = (const float*)d_in[4];
    const float* wv = (const float*)d_in[5];
    const float* wo = (const float*)d_in[6];
    float* out = (float*)d_out;

    float *qp, *kp, *vp, *ap, *xt, *wqt, *wkt, *wvt, *wot, *qt, *kt;
    cudaGetSymbolAddress((void**)&qp, g_q);
    cudaGetSymbolAddress((void**)&kp, g_k);
    cudaGetSymbolAddress((void**)&vp, g_v);
    cudaGetSymbolAddress((void**)&ap, g_attn);
    cudaGetSymbolAddress((void**)&xt, g_xt);
    cudaGetSymbolAddress((void**)&wqt, g_wqt);
    cudaGetSymbolAddress((void**)&wkt, g_wkt);
    cudaGetSymbolAddress((void**)&wvt, g_wvt);
    cudaGetSymbolAddress((void**)&wot, g_wot);
    cudaGetSymbolAddress((void**)&qt, g_qt);
    cudaGetSymbolAddress((void**)&kt, g_kt);
    __half *vh, *vl;
    cudaGetSymbolAddress((void**)&vh, g_vh);
    cudaGetSymbolAddress((void**)&vl, g_vl);

    cudaFuncSetAttribute(gemm_tf32,
                         cudaFuncAttributeMaxDynamicSharedMemorySize, G3_SMEM);
    cudaFuncSetAttribute(flash_v8,
                         cudaFuncAttributeMaxDynamicSharedMemorySize, FA7_SMEM);

    const int n4_xd = T_ * D_ / 4;
    const int n4_w  = D_ * D_ / 4;
    const int n4_kv = KV_ * HD_ * D_ / 4;
    const int n4_kvt = T_ * KV_ * HD_ / 4;
    // 1/sqrt(128) * log2(e): softmax runs in log2 domain
    const float qscale = 0.08838834764831845f * 1.4426950408889634f;

    round_tf32<<<(n4_xd + 255)/256, 256>>>(x,  xt,  n4_xd);
    round_tf32<<<(n4_w  + 255)/256, 256>>>(wq, wqt, n4_w);
    round_tf32<<<(n4_kv + 255)/256, 256>>>(wk, wkt, n4_kv);
    round_tf32<<<(n4_kv + 255)/256, 256>>>(wv, wvt, n4_kv);
    round_tf32<<<(n4_w  + 255)/256, 256>>>(wo, wot, n4_w);

    dim3 blk(256);
    // Q projection
    gemm_tf32<<<dim3(D_/128, T_/128, 1), blk, G3_SMEM>>>(
        xt, wqt, wqt, qp, qp, D_, D_);
    // fused K+V projections (z selects weight/output)
    gemm_tf32<<<dim3((KV_*HD_)/128, T_/128, 2), blk, G3_SMEM>>>(
        xt, wkt, wvt, kp, vp, KV_*HD_, D_);

    rope_tf32<<<(T_*H_*(HD_/4))/256,  256>>>(qp, qt, fc, fs, H_, qscale);
    rope_tf32<<<(T_*KV_*(HD_/4))/256, 256>>>(kp, kt, fc, fs, KV_, 1.0f);
    split_f16<<<(n4_kvt + 255)/256, 256>>>(vp, vh, vl, n4_kvt);

    flash_v8<<<dim3(S_/128, H_, B_), blk, FA7_SMEM>>>(qt, kt, vh, vl, ap);

    // O projection
    gemm_tf32<<<dim3(D_/128, T_/128, 1), blk, G3_SMEM>>>(
        ap, wot, wot, out, out, D_, D_);
}

// round 10
// speedup vs baseline: 1.5260x; 1.5260x over previous
#include <cuda_runtime.h>
#include <cuda_bf16.h>
#include <cuda_fp16.h>
#include <math.h>
#include <cstdint>

#define B_ 2
#define S_ 2048
#define D_ 4096
#define H_ 32
#define KV_ 8
#define HD_ 128
#define T_ (B_*S_)
#define REP_ (H_/KV_)

// ---------------------------------------------------------------------------
// Scratch (device globals: allocation-free rule)
// ---------------------------------------------------------------------------
__device__ float g_q[T_ * D_];             // Q proj (pre-rope fp32)
__device__ float g_k[T_ * KV_ * HD_];      // K proj (pre-rope fp32)
__device__ float g_v[T_ * KV_ * HD_];      // V proj fp32
__device__ float g_attn[T_ * D_];          // attention out (tf32-rounded)

__device__ float g_xt[T_ * D_];            // tf32-rounded operands
__device__ float g_wqt[D_ * D_];
__device__ float g_wkt[KV_ * HD_ * D_];
__device__ float g_wvt[KV_ * HD_ * D_];
__device__ float g_wot[D_ * D_];

__device__ float g_qt[T_ * D_];            // roped+scaled+rna Q (fp32)
__device__ float g_kt[T_ * KV_ * HD_];     // roped+rna K (fp32)
__device__ __half g_vh[T_ * KV_ * HD_];    // V fp16 hi
__device__ __half g_vl[T_ * KV_ * HD_];    // V fp16 lo

// ---------------------------------------------------------------------------
// Helpers
// ---------------------------------------------------------------------------
__device__ __forceinline__ uint32_t smem_to_u32(const void* smem_ptr) {
    uint32_t addr;
    asm("{ .reg .u64 tmp; cvta.to.shared.u64 tmp, %1; cvt.u32.u64 %0, tmp; }"
        : "=r"(addr) : "l"(smem_ptr));
    return addr;
}
__device__ __forceinline__ void cp_async16(uint32_t saddr, const void* gaddr) {
    asm volatile("cp.async.cg.shared.global [%0], [%1], 16;"
                 :: "r"(saddr), "l"(gaddr));
}
#define CP_COMMIT() asm volatile("cp.async.commit_group;")
#define CP_WAIT(n)  asm volatile("cp.async.wait_group %0;" :: "n"(n))

__device__ __forceinline__ uint32_t lds32(uint32_t addr) {
    uint32_t v;
    asm("ld.shared.b32 %0, [%1];" : "=r"(v) : "r"(addr));
    return v;
}

#define MMA_TF32(d, a, b) \
    asm volatile("mma.sync.aligned.m16n8k8.row.col.f32.tf32.tf32.f32 " \
        "{%0,%1,%2,%3}, {%4,%5,%6,%7}, {%8,%9}, {%0,%1,%2,%3};" \
        : "+f"((d)[0]), "+f"((d)[1]), "+f"((d)[2]), "+f"((d)[3]) \
        : "r"((a)[0]), "r"((a)[1]), "r"((a)[2]), "r"((a)[3]), \
          "r"((b)[0]), "r"((b)[1]))

#define MMA_TF32_2(d, a0, a1, a2, a3, bb0, bb1) \
    asm volatile("mma.sync.aligned.m16n8k8.row.col.f32.tf32.tf32.f32 " \
        "{%0,%1,%2,%3}, {%4,%5,%6,%7}, {%8,%9}, {%0,%1,%2,%3};" \
        : "+f"((d)[0]), "+f"((d)[1]), "+f"((d)[2]), "+f"((d)[3]) \
        : "r"(a0), "r"(a1), "r"(a2), "r"(a3), "r"(bb0), "r"(bb1))

#define MMA_F16(d, a, bb0, bb1) \
    asm volatile("mma.sync.aligned.m16n8k16.row.col.f32.f16.f16.f32 " \
        "{%0,%1,%2,%3}, {%4,%5,%6,%7}, {%8,%9}, {%0,%1,%2,%3};" \
        : "+f"((d)[0]), "+f"((d)[1]), "+f"((d)[2]), "+f"((d)[3]) \
        : "r"((a)[0]), "r"((a)[1]), "r"((a)[2]), "r"((a)[3]), \
          "r"(bb0), "r"(bb1))

#define LDSM4(d0,d1,d2,d3,a) \
    asm volatile("ldmatrix.sync.aligned.m8n8.x4.shared.b16 {%0,%1,%2,%3}, [%4];" \
        : "=r"(d0), "=r"(d1), "=r"(d2), "=r"(d3) : "r"(a))
#define LDSM4T(d0,d1,d2,d3,a) \
    asm volatile("ldmatrix.sync.aligned.m8n8.x4.trans.shared.b16 {%0,%1,%2,%3}, [%4];" \
        : "=r"(d0), "=r"(d1), "=r"(d2), "=r"(d3) : "r"(a))

__device__ __forceinline__ uint32_t packf16(float lo, float hi) {
    uint32_t r;
    asm("cvt.rn.f16x2.f32 %0, %1, %2;" : "=r"(r) : "f"(hi), "f"(lo));
    return r;
}
__device__ __forceinline__ float f16_round(float x) {
    return __half2float(__float2half(x));
}
__device__ __forceinline__ uint32_t tf32_rna(float x) {
    uint32_t r;
    asm("cvt.rna.tf32.f32 %0, %1;" : "=r"(r) : "f"(x));
    return r;
}

// ---------------------------------------------------------------------------
// fp32 -> tf32 rounding
// ---------------------------------------------------------------------------
__global__ void round_tf32(const float* __restrict__ X, float* __restrict__ Y, int n4)
{
    int i = blockIdx.x * blockDim.x + threadIdx.x;
    if (i >= n4) return;
    float4 v = reinterpret_cast<const float4*>(X)[i];
    uint4 o;
    o.x = tf32_rna(v.x); o.y = tf32_rna(v.y);
    o.z = tf32_rna(v.z); o.w = tf32_rna(v.w);
    reinterpret_cast<uint4*>(Y)[i] = o;
}

// ---------------------------------------------------------------------------
// fp32 -> fp16 hi/lo split (V)
// ---------------------------------------------------------------------------
__global__ void split_f16(const float* __restrict__ X,
                          __half* __restrict__ Hh, __half* __restrict__ Ll, int n4)
{
    int i = blockIdx.x * blockDim.x + threadIdx.x;
    if (i >= n4) return;
    float4 v = reinterpret_cast<const float4*>(X)[i];
    __half h0 = __float2half(v.x), h1 = __float2half(v.y);
    __half h2 = __float2half(v.z), h3 = __float2half(v.w);
    __half l0 = __float2half(v.x - __half2float(h0));
    __half l1 = __float2half(v.y - __half2float(h1));
    __half l2 = __float2half(v.z - __half2float(h2));
    __half l3 = __float2half(v.w - __half2float(h3));
    ushort4 hp, lp;
    hp.x = __half_as_ushort(h0); hp.y = __half_as_ushort(h1);
    hp.z = __half_as_ushort(h2); hp.w = __half_as_ushort(h3);
    lp.x = __half_as_ushort(l0); lp.y = __half_as_ushort(l1);
    lp.z = __half_as_ushort(l2); lp.w = __half_as_ushort(l3);
    reinterpret_cast<ushort4*>(Hh)[i] = hp;
    reinterpret_cast<ushort4*>(Ll)[i] = lp;
}

// ---------------------------------------------------------------------------
// Fused RoPE (+scale) + tf32 rounding, fp32 out
// ---------------------------------------------------------------------------
__global__ void rope_tf32(const float* __restrict__ src, float* __restrict__ dst,
                          const float* __restrict__ fc, const float* __restrict__ fs,
                          int heads, float sc)
{
    int idx = blockIdx.x * blockDim.x + threadIdx.x;
    int total = T_ * heads * (HD_/4);
    if (idx >= total) return;
    int i32 = idx & 31;
    int rem = idx >> 5;
    int h   = rem % heads;
    int t   = rem / heads;
    int s   = t & (S_ - 1);
    int p0  = 2 * i32;
    float c0 = fc[s*64 + p0],     s0 = fs[s*64 + p0];
    float c1 = fc[s*64 + p0 + 1], s1 = fs[s*64 + p0 + 1];
    size_t base = (size_t)t * heads * HD_ + h * HD_ + 4*i32;
    float4 v = *reinterpret_cast<const float4*>(src + base);
    uint4 o;
    o.x = tf32_rna((v.x * c0 - v.y * s0) * sc);
    o.y = tf32_rna((v.x * s0 + v.y * c0) * sc);
    o.z = tf32_rna((v.z * c1 - v.w * s1) * sc);
    o.w = tf32_rna((v.z * s1 + v.w * c1) * sc);
    *reinterpret_cast<uint4*>(dst + base) = o;
}

// ---------------------------------------------------------------------------
// tf32 GEMM (exact R5 config — measured fastest): C = A @ W^T
// CTA 128x128, BK=64 floats, 3-stage cp.async, scalar-lds fragments.
// ---------------------------------------------------------------------------
#define AT_BYTES (128 * 256)
#define STG_BYTES (2 * AT_BYTES)
#define G3_SMEM (3 * STG_BYTES)

__device__ __forceinline__ void gemm_stage_copy(
    uint32_t sbase, const float* __restrict__ A128, const float* __restrict__ B128,
    int K, int k0, int tid)
{
    #pragma unroll
    for (int t = 0; t < 2; t++) {
        const float* src = t ? B128 : A128;
        #pragma unroll
        for (int it = 0; it < 8; it++) {
            int idx = it * 256 + tid;
            int row = idx >> 4;
            int gr  = idx & 15;
            uint32_t dst = sbase + t * AT_BYTES + row * 256 +
                           (uint32_t)((gr * 16) ^ ((row & 7) << 4));
            cp_async16(dst, src + (size_t)row * K + k0 + gr * 4);
        }
    }
}

__global__ void __launch_bounds__(256, 1)
gemm_tf32(const float* __restrict__ A, const float* __restrict__ Bw,
          float* __restrict__ C, int M, int N, int K)
{
    extern __shared__ __align__(1024) char smem[];
    const uint32_t sb0 = smem_to_u32(smem);
    const int tid  = threadIdx.x;
    const int wid  = tid >> 5;
    const int lane = tid & 31;
    const int bm = blockIdx.y * 128;
    const int bn = blockIdx.x * 128;
    const int warp_m = (wid >> 2) * 64;
    const int warp_n = (wid & 3) * 32;
    const int NC = K >> 6;

    const float* A128 = A  + (size_t)bm * K;
    const float* B128 = Bw + (size_t)bn * K;

    float acc[4][4][4];
    #pragma unroll
    for (int i = 0; i < 4; i++)
        #pragma unroll
        for (int j = 0; j < 4; j++)
            #pragma unroll
            for (int r = 0; r < 4; r++) acc[i][j][r] = 0.f;

    const int grp  = lane >> 2;
    const int krem = (lane & 3) * 4;

    gemm_stage_copy(sb0, A128, B128, K, 0, tid);
    CP_COMMIT();
    gemm_stage_copy(sb0 + STG_BYTES, A128, B128, K, 64, tid);
    CP_COMMIT();

    int stage = 0;
    for (int c = 0; c < NC; c++) {
        if (c + 1 < NC) { CP_WAIT(1); } else { CP_WAIT(0); }
        __syncthreads();
        if (c + 2 < NC) {
            int ns = stage + 2; if (ns >= 3) ns -= 3;
            gemm_stage_copy(sb0 + ns * STG_BYTES, A128, B128, K, (c + 2) << 6, tid);
            CP_COMMIT();
        }
        const uint32_t sb = sb0 + stage * STG_BYTES;
        if (++stage == 3) stage = 0;

        #pragma unroll
        for (int ks = 0; ks < 8; ks++) {
            const uint32_t kbyte = ks * 32;
            uint32_t a[4][4], bfr[4][2];
            #pragma unroll
            for (int mt = 0; mt < 4; mt++) {
                int row = warp_m + mt * 16 + grp;
                uint32_t base  = sb + row * 256;
                uint32_t swz   = (uint32_t)((row & 7) << 4);
                a[mt][0] = lds32(base        + ((kbyte + krem)      ^ swz));
                a[mt][1] = lds32(base + 2048 + ((kbyte + krem)      ^ swz));
                a[mt][2] = lds32(base        + ((kbyte + 16 + krem) ^ swz));
                a[mt][3] = lds32(base + 2048 + ((kbyte + 16 + krem) ^ swz));
            }
            #pragma unroll
            for (int nt = 0; nt < 4; nt++) {
                int n = warp_n + nt * 8 + grp;
                uint32_t base = sb + AT_BYTES + n * 256;
                uint32_t swz  = (uint32_t)((n & 7) << 4);
                bfr[nt][0] = lds32(base + ((kbyte + krem)      ^ swz));
                bfr[nt][1] = lds32(base + ((kbyte + 16 + krem) ^ swz));
            }
            #pragma unroll
            for (int mt = 0; mt < 4; mt++)
                #pragma unroll
                for (int nt = 0; nt < 4; nt++)
                    MMA_TF32(acc[mt][nt], a[mt], bfr[nt]);
        }
    }

    #pragma unroll
    for (int mt = 0; mt < 4; mt++) {
        int row = bm + warp_m + mt * 16 + grp;
        #pragma unroll
        for (int nt = 0; nt < 4; nt++) {
            int col = bn + warp_n + nt * 8 + (lane & 3) * 2;
            *(float2*)(C + (size_t)row * N + col) =
                make_float2(acc[mt][nt][0], acc[mt][nt][1]);
            *(float2*)(C + (size_t)(row + 8) * N + col) =
                make_float2(acc[mt][nt][2], acc[mt][nt][3]);
        }
    }
}

// ---------------------------------------------------------------------------
// Flash attention (R8-winning config): QK^T tf32 single-pass, PV fp16 3-term,
// __expf softmax. Single change vs 2465us kernel: l-sum kept thread-local
// per tile (lsum = lsum*a + local), warp-reduced ONCE in the epilogue.
// ---------------------------------------------------------------------------
#define FQ7 (128 * 512)            // Q fp32
#define FK7 (64 * 512)             // K fp32
#define FV7 (64 * 256)             // V fp16 (per hi/lo)
#define FST7 (FK7 + 2 * FV7)       // 64KB per stage
#define FA7_SMEM (FQ7 + 2 * FST7)  // 196608

__device__ __forceinline__ void fa7_load_kv(
    uint32_t sbase, const float* __restrict__ Kt,
    const __half* __restrict__ Vh, const __half* __restrict__ Vl,
    int tk0, int g, int tid)
{
    const float* ks = Kt + (size_t)tk0 * (KV_*HD_) + g * HD_;
    #pragma unroll
    for (int it = 0; it < 8; it++) {
        int idx = it * 256 + tid;
        int row = idx >> 5, ch = idx & 31;
        uint32_t dst = sbase + row * 512 + (uint32_t)((ch * 16) ^ ((row & 7) << 4));
        cp_async16(dst, ks + (size_t)row * (KV_*HD_) + ch * 4);
    }
    const __half* vs[2] = {Vh + (size_t)tk0 * (KV_*HD_) + g * HD_,
                           Vl + (size_t)tk0 * (KV_*HD_) + g * HD_};
    #pragma unroll
    for (int t = 0; t < 2; t++) {
        #pragma unroll
        for (int it = 0; it < 4; it++) {
            int idx = it * 256 + tid;
            int row = idx >> 4, ch = idx & 15;
            uint32_t dst = sbase + FK7 + t * FV7 + row * 256 +
                           (uint32_t)((ch * 16) ^ ((row & 7) << 4));
            cp_async16(dst, vs[t] + (size_t)row * (KV_*HD_) + ch * 8);
        }
    }
}

__global__ void __launch_bounds__(256, 1)
flash_v10(const float* __restrict__ Qt, const float* __restrict__ Kt,
          const __half* __restrict__ Vh, const __half* __restrict__ Vl,
          float* __restrict__ Og)
{
    extern __shared__ __align__(1024) char fsm[];
    const uint32_t sb = smem_to_u32(fsm);
    const int tid  = threadIdx.x;
    const int wid  = tid >> 5;
    const int lane = tid & 31;
    const int qt = (gridDim.x - 1) - blockIdx.x;   // heavy tiles first
    const int h  = blockIdx.y;
    const int b  = blockIdx.z;
    const int g  = h / REP_;
    const int q0 = qt * 128;
    const int t0 = b * S_ + q0;
    const int nt = 2 * qt + 2;

    const int l7 = lane & 7;
    const int arow = 16 * wid + (lane & 15);
    const uint32_t achk = (lane >= 16) ? 16u : 0u;
    const uint32_t aswz = (uint32_t)((arow & 7) << 4);
    const uint32_t kchk = (uint32_t)((lane >> 3) * 16);
    const uint32_t kswz = (uint32_t)(l7 << 4);
    const int vrow_l = l7 + ((lane >> 3) & 1) * 8;
    const int vgsel  = (lane >= 16) ? 16 : 0;
    const uint32_t vswz = (uint32_t)(l7 << 4);

    fa7_load_kv(sb + FQ7, Kt, Vh, Vl, b * S_, g, tid);
    CP_COMMIT();
    {   // stage Q (fp32, 128 rows x 512B)
        const float* src = Qt + (size_t)t0 * D_ + h * HD_;
        #pragma unroll
        for (int it = 0; it < 16; it++) {
            int idx = it * 256 + tid;
            int row = idx >> 5, ch = idx & 31;
            uint32_t dst = sb + row * 512 + (uint32_t)((ch * 16) ^ ((row & 7) << 4));
            cp_async16(dst, src + (size_t)row * D_ + ch * 4);
        }
        CP_COMMIT();
    }

    float o[16][4];
    #pragma unroll
    for (int f = 0; f < 16; f++)
        #pragma unroll
        for (int r = 0; r < 4; r++) o[f][r] = 0.f;
    float m0 = -1e30f, m1 = -1e30f;
    float lsum0 = 0.f, lsum1 = 0.f;    // thread-local; reduced in epilogue

    const int r0g = q0 + 16 * wid + (lane >> 2);
    const int c0l = (lane & 3) * 2;

    for (int t = 0; t < nt; t++) {
        CP_WAIT(0);
        __syncthreads();
        if (t + 1 < nt) {
            fa7_load_kv(sb + FQ7 + ((t + 1) & 1) * FST7,
                        Kt, Vh, Vl, b * S_ + (t + 1) * 64, g, tid);
            CP_COMMIT();
        }

        const uint32_t kb  = sb + FQ7 + (t & 1) * FST7;
        const uint32_t vhb = kb + FK7;

        float s[8][4];
        #pragma unroll
        for (int j = 0; j < 8; j++)
            #pragma unroll
            for (int r = 0; r < 4; r++) s[j][r] = 0.f;

        // ---- S = Q K^T (tf32, single pass) ----
        #pragma unroll
        for (int dk = 0; dk < 8; dk++) {
            const uint32_t kbyte = (uint32_t)(dk * 64);
            uint32_t qa0[4], qa1[4];
            LDSM4(qa0[0], qa0[1], qa0[2], qa0[3],
                  sb + arow * 512 + ((kbyte + achk) ^ aswz));
            LDSM4(qa1[0], qa1[1], qa1[2], qa1[3],
                  sb + arow * 512 + ((kbyte + 32 + achk) ^ aswz));
            #pragma unroll
            for (int np = 0; np < 8; np++) {
                uint32_t b0, b1, b2, b3;
                LDSM4(b0, b1, b2, b3,
                      kb + (np * 8 + l7) * 512 + ((kbyte + kchk) ^ kswz));
                MMA_TF32_2(s[np], qa0[0], qa0[1], qa0[2], qa0[3], b0, b1);
                MMA_TF32_2(s[np], qa1[0], qa1[1], qa1[2], qa1[3], b2, b3);
            }
        }

        if (t >= 2 * qt) {   // diagonal tile: causal mask
            const int k0 = t * 64;
            #pragma unroll
            for (int j = 0; j < 8; j++) {
                int cg = k0 + 8 * j + c0l;
                if (cg     > r0g)     s[j][0] = -1e30f;
                if (cg + 1 > r0g)     s[j][1] = -1e30f;
                if (cg     > r0g + 8) s[j][2] = -1e30f;
                if (cg + 1 > r0g + 8) s[j][3] = -1e30f;
            }
        }

        // ---- online softmax ----
        float rm0 = -1e30f, rm1 = -1e30f;
        #pragma unroll
        for (int j = 0; j < 8; j++) {
            rm0 = fmaxf(rm0, fmaxf(s[j][0], s[j][1]));
            rm1 = fmaxf(rm1, fmaxf(s[j][2], s[j][3]));
        }
        rm0 = fmaxf(rm0, __shfl_xor_sync(0xffffffffu, rm0, 1));
        rm0 = fmaxf(rm0, __shfl_xor_sync(0xffffffffu, rm0, 2));
        rm1 = fmaxf(rm1, __shfl_xor_sync(0xffffffffu, rm1, 1));
        rm1 = fmaxf(rm1, __shfl_xor_sync(0xffffffffu, rm1, 2));
        float mn0 = fmaxf(m0, rm0), mn1 = fmaxf(m1, rm1);
        float a0 = __expf(m0 - mn0), a1 = __expf(m1 - mn1);
        m0 = mn0; m1 = mn1;
        float sum0 = 0.f, sum1 = 0.f;
        #pragma unroll
        for (int j = 0; j < 8; j++) {
            s[j][0] = __expf(s[j][0] - mn0);
            s[j][1] = __expf(s[j][1] - mn0);
            s[j][2] = __expf(s[j][2] - mn1);
            s[j][3] = __expf(s[j][3] - mn1);
            sum0 += s[j][0] + s[j][1];
            sum1 += s[j][2] + s[j][3];
        }
        lsum0 = lsum0 * a0 + sum0;     // deferred: no per-tile shuffles
        lsum1 = lsum1 * a1 + sum1;
        #pragma unroll
        for (int f = 0; f < 16; f++) {
            o[f][0] *= a0; o[f][1] *= a0;
            o[f][2] *= a1; o[f][3] *= a1;
        }

        // ---- O += P V (fp16 3-term: PhVh + PlVh + PhVl) ----
        #pragma unroll
        for (int kk = 0; kk < 4; kk++) {
            uint32_t ah[4], al[4];
            float p00 = s[2*kk][0],   p01 = s[2*kk][1];
            float p02 = s[2*kk][2],   p03 = s[2*kk][3];
            float p10 = s[2*kk+1][0], p11 = s[2*kk+1][1];
            float p12 = s[2*kk+1][2], p13 = s[2*kk+1][3];
            ah[0] = packf16(p00, p01);
            ah[1] = packf16(p02, p03);
            ah[2] = packf16(p10, p11);
            ah[3] = packf16(p12, p13);
            al[0] = packf16(p00 - f16_round(p00), p01 - f16_round(p01));
            al[1] = packf16(p02 - f16_round(p02), p03 - f16_round(p03));
            al[2] = packf16(p10 - f16_round(p10), p11 - f16_round(p11));
            al[3] = packf16(p12 - f16_round(p12), p13 - f16_round(p13));
            #pragma unroll
            for (int dgp = 0; dgp < 8; dgp++) {
                uint32_t va = vhb + (kk * 16 + vrow_l) * 256 +
                              (uint32_t)(((dgp * 32) + vgsel) ^ vswz);
                uint32_t b0, b1, b2, b3, c0, c1, c2, c3;
                LDSM4T(b0, b1, b2, b3, va);
                LDSM4T(c0, c1, c2, c3, va + FV7);
                MMA_F16(o[2*dgp],   ah, b0, b1);
                MMA_F16(o[2*dgp],   al, b0, b1);
                MMA_F16(o[2*dgp],   ah, c0, c1);
                MMA_F16(o[2*dgp+1], ah, b2, b3);
                MMA_F16(o[2*dgp+1], al, b2, b3);
                MMA_F16(o[2*dgp+1], ah, c2, c3);
            }
        }
    }

    // epilogue: reduce l once, normalize + tf32-round (feeds O-proj GEMM)
    lsum0 += __shfl_xor_sync(0xffffffffu, lsum0, 1);
    lsum0 += __shfl_xor_sync(0xffffffffu, lsum0, 2);
    lsum1 += __shfl_xor_sync(0xffffffffu, lsum1, 1);
    lsum1 += __shfl_xor_sync(0xffffffffu, lsum1, 2);
    const float inv0 = 1.0f / lsum0;
    const float inv1 = 1.0f / lsum1;
    const int rowg = t0 + 16 * wid + (lane >> 2);
    #pragma unroll
    for (int dg = 0; dg < 16; dg++) {
        int col = h * HD_ + dg * 8 + (lane & 3) * 2;
        *(float2*)(Og + (size_t)rowg * D_ + col) = make_float2(
            __uint_as_float(tf32_rna(o[dg][0] * inv0)),
            __uint_as_float(tf32_rna(o[dg][1] * inv0)));
        *(float2*)(Og + (size_t)(rowg + 8) * D_ + col) = make_float2(
            __uint_as_float(tf32_rna(o[dg][2] * inv1)),
            __uint_as_float(tf32_rna(o[dg][3] * inv1)));
    }
}

// ---------------------------------------------------------------------------
extern "C" void kernel_launch(void* const* d_in, const int* in_sizes, int n_in,
                              void* d_out, int out_size)
{
    const float* x  = (const float*)d_in[0];
    const float* fc = (const float*)d_in[1];
    const float* fs = (const float*)d_in[2];
    const float* wq = (const float*)d_in[3];
    const float* wk = (const float*)d_in[4];
    const float* wv = (const float*)d_in[5];
    const float* wo = (const float*)d_in[6];
    float* out = (float*)d_out;

    float *qp, *kp, *vp, *ap, *xt, *wqt, *wkt, *wvt, *wot, *qt, *kt;
    cudaGetSymbolAddress((void**)&qp, g_q);
    cudaGetSymbolAddress((void**)&kp, g_k);
    cudaGetSymbolAddress((void**)&vp, g_v);
    cudaGetSymbolAddress((void**)&ap, g_attn);
    cudaGetSymbolAddress((void**)&xt, g_xt);
    cudaGetSymbolAddress((void**)&wqt, g_wqt);
    cudaGetSymbolAddress((void**)&wkt, g_wkt);
    cudaGetSymbolAddress((void**)&wvt, g_wvt);
    cudaGetSymbolAddress((void**)&wot, g_wot);
    cudaGetSymbolAddress((void**)&qt, g_qt);
    cudaGetSymbolAddress((void**)&kt, g_kt);
    __half *vh, *vl;
    cudaGetSymbolAddress((void**)&vh, g_vh);
    cudaGetSymbolAddress((void**)&vl, g_vl);

    cudaFuncSetAttribute(gemm_tf32,
                         cudaFuncAttributeMaxDynamicSharedMemorySize, G3_SMEM);
    cudaFuncSetAttribute(flash_v10,
                         cudaFuncAttributeMaxDynamicSharedMemorySize, FA7_SMEM);

    const int n4_xd = T_ * D_ / 4;
    const int n4_w  = D_ * D_ / 4;
    const int n4_kv = KV_ * HD_ * D_ / 4;
    const int n4_kvt = T_ * KV_ * HD_ / 4;
    const float scale = 0.08838834764831845f;  // 1/sqrt(128)

    round_tf32<<<(n4_xd + 255)/256, 256>>>(x,  xt,  n4_xd);
    round_tf32<<<(n4_w  + 255)/256, 256>>>(wq, wqt, n4_w);
    round_tf32<<<(n4_kv + 255)/256, 256>>>(wk, wkt, n4_kv);
    round_tf32<<<(n4_kv + 255)/256, 256>>>(wv, wvt, n4_kv);
    round_tf32<<<(n4_w  + 255)/256, 256>>>(wo, wot, n4_w);

    dim3 blk(256);
    gemm_tf32<<<dim3(D_/128, T_/128), blk, G3_SMEM>>>(xt, wqt, qp, T_, D_, D_);
    gemm_tf32<<<dim3((KV_*HD_)/128, T_/128), blk, G3_SMEM>>>(xt, wkt, kp, T_, KV_*HD_, D_);
    gemm_tf32<<<dim3((KV_*HD_)/128, T_/128), blk, G3_SMEM>>>(xt, wvt, vp, T_, KV_*HD_, D_);

    rope_tf32<<<(T_*H_*(HD_/4))/256,  256>>>(qp, qt, fc, fs, H_, scale);
    rope_tf32<<<(T_*KV_*(HD_/4))/256, 256>>>(kp, kt, fc, fs, KV_, 1.0f);
    split_f16<<<(n4_kvt + 255)/256, 256>>>(vp, vh, vl, n4_kvt);

    flash_v10<<<dim3(S_/128, H_, B_), blk, FA7_SMEM>>>(qt, kt, vh, vl, ap);

    gemm_tf32<<<dim3(D_/128, T_/128), blk, G3_SMEM>>>(ap, wot, out, T_, D_, D_);
}

// round 11
// speedup vs baseline: 2.3357x; 1.5306x over previous
#include <cuda_runtime.h>
#include <cuda_bf16.h>
#include <cuda_fp16.h>
#include <math.h>
#include <cstdint>

#define B_ 2
#define S_ 2048
#define D_ 4096
#define H_ 32
#define KV_ 8
#define HD_ 128
#define T_ (B_*S_)
#define REP_ (H_/KV_)

// ---------------------------------------------------------------------------
// Scratch (device globals: allocation-free rule)
// ---------------------------------------------------------------------------
__device__ float g_q[T_ * D_];             // Q proj (pre-rope fp32)
__device__ float g_k[T_ * KV_ * HD_];      // K proj (pre-rope fp32)
__device__ float g_v[T_ * KV_ * HD_];      // V proj fp32
__device__ __half g_attn16[T_ * D_];       // attention out (fp16, feeds O-proj)

__device__ __half g_x16[T_ * D_];          // fp16 GEMM operands
__device__ __half g_wq16[D_ * D_];
__device__ __half g_wk16[KV_ * HD_ * D_];
__device__ __half g_wv16[KV_ * HD_ * D_];
__device__ __half g_wo16[D_ * D_];

__device__ float g_qt[T_ * D_];            // roped+scaled+rna Q (fp32)
__device__ float g_kt[T_ * KV_ * HD_];     // roped+rna K (fp32)
__device__ __half g_vh[T_ * KV_ * HD_];    // V fp16 hi
__device__ __half g_vl[T_ * KV_ * HD_];    // V fp16 lo

// ---------------------------------------------------------------------------
// Helpers
// ---------------------------------------------------------------------------
__device__ __forceinline__ uint32_t smem_to_u32(const void* smem_ptr) {
    uint32_t addr;
    asm("{ .reg .u64 tmp; cvta.to.shared.u64 tmp, %1; cvt.u32.u64 %0, tmp; }"
        : "=r"(addr) : "l"(smem_ptr));
    return addr;
}
__device__ __forceinline__ void cp_async16(uint32_t saddr, const void* gaddr) {
    asm volatile("cp.async.cg.shared.global [%0], [%1], 16;"
                 :: "r"(saddr), "l"(gaddr));
}
#define CP_COMMIT() asm volatile("cp.async.commit_group;")
#define CP_WAIT(n)  asm volatile("cp.async.wait_group %0;" :: "n"(n))

__device__ __forceinline__ uint32_t lds32(uint32_t addr) {
    uint32_t v;
    asm("ld.shared.b32 %0, [%1];" : "=r"(v) : "r"(addr));
    return v;
}

#define MMA_TF32_2(d, a0, a1, a2, a3, bb0, bb1) \
    asm volatile("mma.sync.aligned.m16n8k8.row.col.f32.tf32.tf32.f32 " \
        "{%0,%1,%2,%3}, {%4,%5,%6,%7}, {%8,%9}, {%0,%1,%2,%3};" \
        : "+f"((d)[0]), "+f"((d)[1]), "+f"((d)[2]), "+f"((d)[3]) \
        : "r"(a0), "r"(a1), "r"(a2), "r"(a3), "r"(bb0), "r"(bb1))

#define MMA_F16(d, a, bb0, bb1) \
    asm volatile("mma.sync.aligned.m16n8k16.row.col.f32.f16.f16.f32 " \
        "{%0,%1,%2,%3}, {%4,%5,%6,%7}, {%8,%9}, {%0,%1,%2,%3};" \
        : "+f"((d)[0]), "+f"((d)[1]), "+f"((d)[2]), "+f"((d)[3]) \
        : "r"((a)[0]), "r"((a)[1]), "r"((a)[2]), "r"((a)[3]), \
          "r"(bb0), "r"(bb1))

#define LDSM4(d0,d1,d2,d3,a) \
    asm volatile("ldmatrix.sync.aligned.m8n8.x4.shared.b16 {%0,%1,%2,%3}, [%4];" \
        : "=r"(d0), "=r"(d1), "=r"(d2), "=r"(d3) : "r"(a))
#define LDSM4T(d0,d1,d2,d3,a) \
    asm volatile("ldmatrix.sync.aligned.m8n8.x4.trans.shared.b16 {%0,%1,%2,%3}, [%4];" \
        : "=r"(d0), "=r"(d1), "=r"(d2), "=r"(d3) : "r"(a))

__device__ __forceinline__ uint32_t packf16(float lo, float hi) {
    uint32_t r;
    asm("cvt.rn.f16x2.f32 %0, %1, %2;" : "=r"(r) : "f"(hi), "f"(lo));
    return r;
}
__device__ __forceinline__ float f16_round(float x) {
    return __half2float(__float2half(x));
}
__device__ __forceinline__ uint32_t tf32_rna(float x) {
    uint32_t r;
    asm("cvt.rna.tf32.f32 %0, %1;" : "=r"(r) : "f"(x));
    return r;
}

// ---------------------------------------------------------------------------
// fp32 -> fp16 convert (GEMM operands)
// ---------------------------------------------------------------------------
__global__ void to_f16(const float* __restrict__ X, __half* __restrict__ Y, int n4)
{
    int i = blockIdx.x * blockDim.x + threadIdx.x;
    if (i >= n4) return;
    float4 v = reinterpret_cast<const float4*>(X)[i];
    uint2 o;
    o.x = packf16(v.x, v.y);
    o.y = packf16(v.z, v.w);
    reinterpret_cast<uint2*>(Y)[i] = o;
}

// ---------------------------------------------------------------------------
// fp32 -> fp16 hi/lo split (V)
// ---------------------------------------------------------------------------
__global__ void split_f16(const float* __restrict__ X,
                          __half* __restrict__ Hh, __half* __restrict__ Ll, int n4)
{
    int i = blockIdx.x * blockDim.x + threadIdx.x;
    if (i >= n4) return;
    float4 v = reinterpret_cast<const float4*>(X)[i];
    __half h0 = __float2half(v.x), h1 = __float2half(v.y);
    __half h2 = __float2half(v.z), h3 = __float2half(v.w);
    __half l0 = __float2half(v.x - __half2float(h0));
    __half l1 = __float2half(v.y - __half2float(h1));
    __half l2 = __float2half(v.z - __half2float(h2));
    __half l3 = __float2half(v.w - __half2float(h3));
    ushort4 hp, lp;
    hp.x = __half_as_ushort(h0); hp.y = __half_as_ushort(h1);
    hp.z = __half_as_ushort(h2); hp.w = __half_as_ushort(h3);
    lp.x = __half_as_ushort(l0); lp.y = __half_as_ushort(l1);
    lp.z = __half_as_ushort(l2); lp.w = __half_as_ushort(l3);
    reinterpret_cast<ushort4*>(Hh)[i] = hp;
    reinterpret_cast<ushort4*>(Ll)[i] = lp;
}

// ---------------------------------------------------------------------------
// Fused RoPE (+scale) + tf32 rounding, fp32 out (flash QK operands)
// ---------------------------------------------------------------------------
__global__ void rope_tf32(const float* __restrict__ src, float* __restrict__ dst,
                          const float* __restrict__ fc, const float* __restrict__ fs,
                          int heads, float sc)
{
    int idx = blockIdx.x * blockDim.x + threadIdx.x;
    int total = T_ * heads * (HD_/4);
    if (idx >= total) return;
    int i32 = idx & 31;
    int rem = idx >> 5;
    int h   = rem % heads;
    int t   = rem / heads;
    int s   = t & (S_ - 1);
    int p0  = 2 * i32;
    float c0 = fc[s*64 + p0],     s0 = fs[s*64 + p0];
    float c1 = fc[s*64 + p0 + 1], s1 = fs[s*64 + p0 + 1];
    size_t base = (size_t)t * heads * HD_ + h * HD_ + 4*i32;
    float4 v = *reinterpret_cast<const float4*>(src + base);
    uint4 o;
    o.x = tf32_rna((v.x * c0 - v.y * s0) * sc);
    o.y = tf32_rna((v.x * s0 + v.y * c0) * sc);
    o.z = tf32_rna((v.z * c1 - v.w * s1) * sc);
    o.w = tf32_rna((v.z * s1 + v.w * c1) * sc);
    *reinterpret_cast<uint4*>(dst + base) = o;
}

// ---------------------------------------------------------------------------
// fp16 single-pass GEMM: C[M,N] = A[M,K] @ W[N,K]^T, fp32 accumulate.
// R3-validated body (CTA 128x128, BK=64, warp tile 64x32, 8 warps,
// double-buffered cp.async, scalar-lds pair fragments), single term.
// ---------------------------------------------------------------------------
#define GT_BYTES 16384                 // one tile: 128 rows x 128B (64 fp16)
#define GSTAGE (2 * GT_BYTES)          // A + B = 32KB
#define GF16_SMEM (2 * GSTAGE)         // 64KB double-buffered

__device__ __forceinline__ void g16_copy(
    uint32_t sbase, const __half* __restrict__ Ab, const __half* __restrict__ Bb,
    int K, int k0, int tid)
{
    #pragma unroll
    for (int t = 0; t < 2; t++) {
        const __half* src = t ? Bb : Ab;
        uint32_t toff = sbase + t * GT_BYTES;
        #pragma unroll
        for (int p = 0; p < 4; p++) {
            int idx = p * 256 + tid;
            int row = idx >> 3;
            int ch  = idx & 7;
            uint32_t dst = toff + row * 128 +
                           (uint32_t)((ch * 16) ^ ((row & 7) << 4));
            cp_async16(dst, src + (size_t)row * K + k0 + ch * 8);
        }
    }
}

__global__ void __launch_bounds__(256)
gemm_f16(const __half* __restrict__ A, const __half* __restrict__ Bw,
         float* __restrict__ C, int M, int N, int K)
{
    extern __shared__ __align__(1024) char smem[];
    const uint32_t sb0 = smem_to_u32(smem);
    const int tid  = threadIdx.x;
    const int wid  = tid >> 5;
    const int lane = tid & 31;
    const int bm = blockIdx.y * 128;
    const int bn = blockIdx.x * 128;
    const int warp_m = (wid >> 2) * 64;
    const int warp_n = (wid & 3) * 32;
    const int NC = K >> 6;

    const __half* Ab = A  + (size_t)bm * K;
    const __half* Bb = Bw + (size_t)bn * K;

    float acc[4][4][4];
    #pragma unroll
    for (int i = 0; i < 4; i++)
        #pragma unroll
        for (int j = 0; j < 4; j++)
            #pragma unroll
            for (int r = 0; r < 4; r++) acc[i][j][r] = 0.f;

    const int lg  = lane >> 2;        // 0..7
    const int lk4 = (lane & 3) * 4;   // k byte offset within 32B group

    g16_copy(sb0, Ab, Bb, K, 0, tid);
    CP_COMMIT();

    for (int c = 0; c < NC; c++) {
        if (c + 1 < NC) {
            g16_copy(sb0 + ((c + 1) & 1) * GSTAGE, Ab, Bb, K, (c + 1) << 6, tid);
            CP_COMMIT();
            CP_WAIT(1);
        } else {
            CP_WAIT(0);
        }
        __syncthreads();

        const uint32_t sb = sb0 + (c & 1) * GSTAGE;

        #pragma unroll
        for (int ks = 0; ks < 4; ks++) {
            const int kb = ks * 32 + lk4;

            uint32_t ah[4][4], bh[4][2];
            #pragma unroll
            for (int mt = 0; mt < 4; mt++) {
                int r0 = warp_m + mt * 16 + lg;
                int r1 = r0 + 8;
                uint32_t rb0 = r0 * 128, rx0 = (r0 & 7) << 4;
                uint32_t rb1 = r1 * 128, rx1 = (r1 & 7) << 4;
                ah[mt][0] = lds32(sb + rb0 + (kb ^ rx0));
                ah[mt][1] = lds32(sb + rb1 + (kb ^ rx1));
                ah[mt][2] = lds32(sb + rb0 + ((kb + 16) ^ rx0));
                ah[mt][3] = lds32(sb + rb1 + ((kb + 16) ^ rx1));
            }
            #pragma unroll
            for (int nt = 0; nt < 4; nt++) {
                int n = warp_n + nt * 8 + lg;
                uint32_t rb = n * 128, rx = (n & 7) << 4;
                bh[nt][0] = lds32(sb + GT_BYTES + rb + (kb ^ rx));
                bh[nt][1] = lds32(sb + GT_BYTES + rb + ((kb + 16) ^ rx));
            }
            #pragma unroll
            for (int mt = 0; mt < 4; mt++)
                #pragma unroll
                for (int nt = 0; nt < 4; nt++)
                    MMA_F16(acc[mt][nt], ah[mt], bh[nt][0], bh[nt][1]);
        }
        __syncthreads();
    }

    #pragma unroll
    for (int mt = 0; mt < 4; mt++) {
        int row = bm + warp_m + mt * 16 + lg;
        #pragma unroll
        for (int nt = 0; nt < 4; nt++) {
            int col = bn + warp_n + nt * 8 + (lane & 3) * 2;
            *(float2*)(C + (size_t)row * N + col) =
                make_float2(acc[mt][nt][0], acc[mt][nt][1]);
            *(float2*)(C + (size_t)(row + 8) * N + col) =
                make_float2(acc[mt][nt][2], acc[mt][nt][3]);
        }
    }
}

// ---------------------------------------------------------------------------
// Flash attention (R10-winning config): QK^T tf32 single-pass, PV fp16 3-term,
// deferred l-sum. Epilogue writes fp16 directly (feeds fp16 O-proj GEMM).
// ---------------------------------------------------------------------------
#define FQ7 (128 * 512)            // Q fp32
#define FK7 (64 * 512)             // K fp32
#define FV7 (64 * 256)             // V fp16 (per hi/lo)
#define FST7 (FK7 + 2 * FV7)       // 64KB per stage
#define FA7_SMEM (FQ7 + 2 * FST7)  // 196608

__device__ __forceinline__ void fa7_load_kv(
    uint32_t sbase, const float* __restrict__ Kt,
    const __half* __restrict__ Vh, const __half* __restrict__ Vl,
    int tk0, int g, int tid)
{
    const float* ks = Kt + (size_t)tk0 * (KV_*HD_) + g * HD_;
    #pragma unroll
    for (int it = 0; it < 8; it++) {
        int idx = it * 256 + tid;
        int row = idx >> 5, ch = idx & 31;
        uint32_t dst = sbase + row * 512 + (uint32_t)((ch * 16) ^ ((row & 7) << 4));
        cp_async16(dst, ks + (size_t)row * (KV_*HD_) + ch * 4);
    }
    const __half* vs[2] = {Vh + (size_t)tk0 * (KV_*HD_) + g * HD_,
                           Vl + (size_t)tk0 * (KV_*HD_) + g * HD_};
    #pragma unroll
    for (int t = 0; t < 2; t++) {
        #pragma unroll
        for (int it = 0; it < 4; it++) {
            int idx = it * 256 + tid;
            int row = idx >> 4, ch = idx & 15;
            uint32_t dst = sbase + FK7 + t * FV7 + row * 256 +
                           (uint32_t)((ch * 16) ^ ((row & 7) << 4));
            cp_async16(dst, vs[t] + (size_t)row * (KV_*HD_) + ch * 8);
        }
    }
}

__global__ void __launch_bounds__(256, 1)
flash_v11(const float* __restrict__ Qt, const float* __restrict__ Kt,
          const __half* __restrict__ Vh, const __half* __restrict__ Vl,
          __half* __restrict__ Og)
{
    extern __shared__ __align__(1024) char fsm[];
    const uint32_t sb = smem_to_u32(fsm);
    const int tid  = threadIdx.x;
    const int wid  = tid >> 5;
    const int lane = tid & 31;
    const int qt = (gridDim.x - 1) - blockIdx.x;   // heavy tiles first
    const int h  = blockIdx.y;
    const int b  = blockIdx.z;
    const int g  = h / REP_;
    const int q0 = qt * 128;
    const int t0 = b * S_ + q0;
    const int nt = 2 * qt + 2;

    const int l7 = lane & 7;
    const int arow = 16 * wid + (lane & 15);
    const uint32_t achk = (lane >= 16) ? 16u : 0u;
    const uint32_t aswz = (uint32_t)((arow & 7) << 4);
    const uint32_t kchk = (uint32_t)((lane >> 3) * 16);
    const uint32_t kswz = (uint32_t)(l7 << 4);
    const int vrow_l = l7 + ((lane >> 3) & 1) * 8;
    const int vgsel  = (lane >= 16) ? 16 : 0;
    const uint32_t vswz = (uint32_t)(l7 << 4);

    fa7_load_kv(sb + FQ7, Kt, Vh, Vl, b * S_, g, tid);
    CP_COMMIT();
    {   // stage Q (fp32, 128 rows x 512B)
        const float* src = Qt + (size_t)t0 * D_ + h * HD_;
        #pragma unroll
        for (int it = 0; it < 16; it++) {
            int idx = it * 256 + tid;
            int row = idx >> 5, ch = idx & 31;
            uint32_t dst = sb + row * 512 + (uint32_t)((ch * 16) ^ ((row & 7) << 4));
            cp_async16(dst, src + (size_t)row * D_ + ch * 4);
        }
        CP_COMMIT();
    }

    float o[16][4];
    #pragma unroll
    for (int f = 0; f < 16; f++)
        #pragma unroll
        for (int r = 0; r < 4; r++) o[f][r] = 0.f;
    float m0 = -1e30f, m1 = -1e30f;
    float lsum0 = 0.f, lsum1 = 0.f;

    const int r0g = q0 + 16 * wid + (lane >> 2);
    const int c0l = (lane & 3) * 2;

    for (int t = 0; t < nt; t++) {
        CP_WAIT(0);
        __syncthreads();
        if (t + 1 < nt) {
            fa7_load_kv(sb + FQ7 + ((t + 1) & 1) * FST7,
                        Kt, Vh, Vl, b * S_ + (t + 1) * 64, g, tid);
            CP_COMMIT();
        }

        const uint32_t kb  = sb + FQ7 + (t & 1) * FST7;
        const uint32_t vhb = kb + FK7;

        float s[8][4];
        #pragma unroll
        for (int j = 0; j < 8; j++)
            #pragma unroll
            for (int r = 0; r < 4; r++) s[j][r] = 0.f;

        // ---- S = Q K^T (tf32, single pass) ----
        #pragma unroll
        for (int dk = 0; dk < 8; dk++) {
            const uint32_t kbyte = (uint32_t)(dk * 64);
            uint32_t qa0[4], qa1[4];
            LDSM4(qa0[0], qa0[1], qa0[2], qa0[3],
                  sb + arow * 512 + ((kbyte + achk) ^ aswz));
            LDSM4(qa1[0], qa1[1], qa1[2], qa1[3],
                  sb + arow * 512 + ((kbyte + 32 + achk) ^ aswz));
            #pragma unroll
            for (int np = 0; np < 8; np++) {
                uint32_t b0, b1, b2, b3;
                LDSM4(b0, b1, b2, b3,
                      kb + (np * 8 + l7) * 512 + ((kbyte + kchk) ^ kswz));
                MMA_TF32_2(s[np], qa0[0], qa0[1], qa0[2], qa0[3], b0, b1);
                MMA_TF32_2(s[np], qa1[0], qa1[1], qa1[2], qa1[3], b2, b3);
            }
        }

        if (t >= 2 * qt) {   // diagonal tile: causal mask
            const int k0 = t * 64;
            #pragma unroll
            for (int j = 0; j < 8; j++) {
                int cg = k0 + 8 * j + c0l;
                if (cg     > r0g)     s[j][0] = -1e30f;
                if (cg + 1 > r0g)     s[j][1] = -1e30f;
                if (cg     > r0g + 8) s[j][2] = -1e30f;
                if (cg + 1 > r0g + 8) s[j][3] = -1e30f;
            }
        }

        // ---- online softmax ----
        float rm0 = -1e30f, rm1 = -1e30f;
        #pragma unroll
        for (int j = 0; j < 8; j++) {
            rm0 = fmaxf(rm0, fmaxf(s[j][0], s[j][1]));
            rm1 = fmaxf(rm1, fmaxf(s[j][2], s[j][3]));
        }
        rm0 = fmaxf(rm0, __shfl_xor_sync(0xffffffffu, rm0, 1));
        rm0 = fmaxf(rm0, __shfl_xor_sync(0xffffffffu, rm0, 2));
        rm1 = fmaxf(rm1, __shfl_xor_sync(0xffffffffu, rm1, 1));
        rm1 = fmaxf(rm1, __shfl_xor_sync(0xffffffffu, rm1, 2));
        float mn0 = fmaxf(m0, rm0), mn1 = fmaxf(m1, rm1);
        float a0 = __expf(m0 - mn0), a1 = __expf(m1 - mn1);
        m0 = mn0; m1 = mn1;
        float sum0 = 0.f, sum1 = 0.f;
        #pragma unroll
        for (int j = 0; j < 8; j++) {
            s[j][0] = __expf(s[j][0] - mn0);
            s[j][1] = __expf(s[j][1] - mn0);
            s[j][2] = __expf(s[j][2] - mn1);
            s[j][3] = __expf(s[j][3] - mn1);
            sum0 += s[j][0] + s[j][1];
            sum1 += s[j][2] + s[j][3];
        }
        lsum0 = lsum0 * a0 + sum0;
        lsum1 = lsum1 * a1 + sum1;
        #pragma unroll
        for (int f = 0; f < 16; f++) {
            o[f][0] *= a0; o[f][1] *= a0;
            o[f][2] *= a1; o[f][3] *= a1;
        }

        // ---- O += P V (fp16 3-term: PhVh + PlVh + PhVl) ----
        #pragma unroll
        for (int kk = 0; kk < 4; kk++) {
            uint32_t ah[4], al[4];
            float p00 = s[2*kk][0],   p01 = s[2*kk][1];
            float p02 = s[2*kk][2],   p03 = s[2*kk][3];
            float p10 = s[2*kk+1][0], p11 = s[2*kk+1][1];
            float p12 = s[2*kk+1][2], p13 = s[2*kk+1][3];
            ah[0] = packf16(p00, p01);
            ah[1] = packf16(p02, p03);
            ah[2] = packf16(p10, p11);
            ah[3] = packf16(p12, p13);
            al[0] = packf16(p00 - f16_round(p00), p01 - f16_round(p01));
            al[1] = packf16(p02 - f16_round(p02), p03 - f16_round(p03));
            al[2] = packf16(p10 - f16_round(p10), p11 - f16_round(p11));
            al[3] = packf16(p12 - f16_round(p12), p13 - f16_round(p13));
            #pragma unroll
            for (int dgp = 0; dgp < 8; dgp++) {
                uint32_t va = vhb + (kk * 16 + vrow_l) * 256 +
                              (uint32_t)(((dgp * 32) + vgsel) ^ vswz);
                uint32_t b0, b1, b2, b3, c0, c1, c2, c3;
                LDSM4T(b0, b1, b2, b3, va);
                LDSM4T(c0, c1, c2, c3, va + FV7);
                MMA_F16(o[2*dgp],   ah, b0, b1);
                MMA_F16(o[2*dgp],   al, b0, b1);
                MMA_F16(o[2*dgp],   ah, c0, c1);
                MMA_F16(o[2*dgp+1], ah, b2, b3);
                MMA_F16(o[2*dgp+1], al, b2, b3);
                MMA_F16(o[2*dgp+1], ah, c2, c3);
            }
        }
    }

    // epilogue: reduce l once, normalize, write fp16 (feeds fp16 O-proj)
    lsum0 += __shfl_xor_sync(0xffffffffu, lsum0, 1);
    lsum0 += __shfl_xor_sync(0xffffffffu, lsum0, 2);
    lsum1 += __shfl_xor_sync(0xffffffffu, lsum1, 1);
    lsum1 += __shfl_xor_sync(0xffffffffu, lsum1, 2);
    const float inv0 = 1.0f / lsum0;
    const float inv1 = 1.0f / lsum1;
    const int rowg = t0 + 16 * wid + (lane >> 2);
    #pragma unroll
    for (int dg = 0; dg < 16; dg++) {
        int col = h * HD_ + dg * 8 + (lane & 3) * 2;
        *reinterpret_cast<uint32_t*>(Og + (size_t)rowg * D_ + col) =
            packf16(o[dg][0] * inv0, o[dg][1] * inv0);
        *reinterpret_cast<uint32_t*>(Og + (size_t)(rowg + 8) * D_ + col) =
            packf16(o[dg][2] * inv1, o[dg][3] * inv1);
    }
}

// ---------------------------------------------------------------------------
extern "C" void kernel_launch(void* const* d_in, const int* in_sizes, int n_in,
                              void* d_out, int out_size)
{
    const float* x  = (const float*)d_in[0];
    const float* fc = (const float*)d_in[1];
    const float* fs = (const float*)d_in[2];
    const float* wq = (const float*)d_in[3];
    const float* wk = (const float*)d_in[4];
    const float* wv = (const float*)d_in[5];
    const float* wo = (const float*)d_in[6];
    float* out = (float*)d_out;

    float *qp, *kp, *vp, *qt, *kt;
    cudaGetSymbolAddress((void**)&qp, g_q);
    cudaGetSymbolAddress((void**)&kp, g_k);
    cudaGetSymbolAddress((void**)&vp, g_v);
    cudaGetSymbolAddress((void**)&qt, g_qt);
    cudaGetSymbolAddress((void**)&kt, g_kt);
    __half *x16, *wq16, *wk16, *wv16, *wo16, *attn16, *vh, *vl;
    cudaGetSymbolAddress((void**)&x16,  g_x16);
    cudaGetSymbolAddress((void**)&wq16, g_wq16);
    cudaGetSymbolAddress((void**)&wk16, g_wk16);
    cudaGetSymbolAddress((void**)&wv16, g_wv16);
    cudaGetSymbolAddress((void**)&wo16, g_wo16);
    cudaGetSymbolAddress((void**)&attn16, g_attn16);
    cudaGetSymbolAddress((void**)&vh, g_vh);
    cudaGetSymbolAddress((void**)&vl, g_vl);

    cudaFuncSetAttribute(gemm_f16,
                         cudaFuncAttributeMaxDynamicSharedMemorySize, GF16_SMEM);
    cudaFuncSetAttribute(flash_v11,
                         cudaFuncAttributeMaxDynamicSharedMemorySize, FA7_SMEM);

    const int n4_xd = T_ * D_ / 4;
    const int n4_w  = D_ * D_ / 4;
    const int n4_kv = KV_ * HD_ * D_ / 4;
    const int n4_kvt = T_ * KV_ * HD_ / 4;
    const float scale = 0.08838834764831845f;  // 1/sqrt(128)

    to_f16<<<(n4_xd + 255)/256, 256>>>(x,  x16,  n4_xd);
    to_f16<<<(n4_w  + 255)/256, 256>>>(wq, wq16, n4_w);
    to_f16<<<(n4_kv + 255)/256, 256>>>(wk, wk16, n4_kv);
    to_f16<<<(n4_kv + 255)/256, 256>>>(wv, wv16, n4_kv);
    to_f16<<<(n4_w  + 255)/256, 256>>>(wo, wo16, n4_w);

    dim3 blk(256);
    gemm_f16<<<dim3(D_/128, T_/128), blk, GF16_SMEM>>>(x16, wq16, qp, T_, D_, D_);
    gemm_f16<<<dim3((KV_*HD_)/128, T_/128), blk, GF16_SMEM>>>(x16, wk16, kp, T_, KV_*HD_, D_);
    gemm_f16<<<dim3((KV_*HD_)/128, T_/128), blk, GF16_SMEM>>>(x16, wv16, vp, T_, KV_*HD_, D_);

    rope_tf32<<<(T_*H_*(HD_/4))/256,  256>>>(qp, qt, fc, fs, H_, scale);
    rope_tf32<<<(T_*KV_*(HD_/4))/256, 256>>>(kp, kt, fc, fs, KV_, 1.0f);
    split_f16<<<(n4_kvt + 255)/256, 256>>>(vp, vh, vl, n4_kvt);

    flash_v11<<<dim3(S_/128, H_, B_), blk, FA7_SMEM>>>(qt, kt, vh, vl, attn16);

    gemm_f16<<<dim3(D_/128, T_/128), blk, GF16_SMEM>>>(attn16, wo16, out, T_, D_, D_);
}

// round 12
// speedup vs baseline: 2.5091x; 1.0742x over previous
#include <cuda_runtime.h>
#include <cuda_bf16.h>
#include <cuda_fp16.h>
#include <math.h>
#include <cstdint>

#define B_ 2
#define S_ 2048
#define D_ 4096
#define H_ 32
#define KV_ 8
#define HD_ 128
#define T_ (B_*S_)
#define REP_ (H_/KV_)

// ---------------------------------------------------------------------------
// Scratch (device globals: allocation-free rule)
// ---------------------------------------------------------------------------
__device__ float g_q[T_ * D_];             // Q proj (pre-rope fp32)
__device__ float g_k[T_ * KV_ * HD_];      // K proj (pre-rope fp32)
__device__ float g_v[T_ * KV_ * HD_];      // V proj fp32
__device__ __half g_attn16[T_ * D_];       // attention out (fp16, feeds O-proj)

__device__ __half g_x16[T_ * D_];          // fp16 GEMM operands
__device__ __half g_wq16[D_ * D_];
__device__ __half g_wk16[KV_ * HD_ * D_];
__device__ __half g_wv16[KV_ * HD_ * D_];
__device__ __half g_wo16[D_ * D_];

__device__ __half g_q16[T_ * D_];          // roped+scaled fp16 Q
__device__ __half g_k16[T_ * KV_ * HD_];   // roped fp16 K
__device__ __half g_vh[T_ * KV_ * HD_];    // V fp16 hi
__device__ __half g_vl[T_ * KV_ * HD_];    // V fp16 lo

// ---------------------------------------------------------------------------
// Helpers
// ---------------------------------------------------------------------------
__device__ __forceinline__ uint32_t smem_to_u32(const void* smem_ptr) {
    uint32_t addr;
    asm("{ .reg .u64 tmp; cvta.to.shared.u64 tmp, %1; cvt.u32.u64 %0, tmp; }"
        : "=r"(addr) : "l"(smem_ptr));
    return addr;
}
__device__ __forceinline__ void cp_async16(uint32_t saddr, const void* gaddr) {
    asm volatile("cp.async.cg.shared.global [%0], [%1], 16;"
                 :: "r"(saddr), "l"(gaddr));
}
#define CP_COMMIT() asm volatile("cp.async.commit_group;")
#define CP_WAIT(n)  asm volatile("cp.async.wait_group %0;" :: "n"(n))

__device__ __forceinline__ uint32_t lds32(uint32_t addr) {
    uint32_t v;
    asm("ld.shared.b32 %0, [%1];" : "=r"(v) : "r"(addr));
    return v;
}

#define MMA_F16(d, a, bb0, bb1) \
    asm volatile("mma.sync.aligned.m16n8k16.row.col.f32.f16.f16.f32 " \
        "{%0,%1,%2,%3}, {%4,%5,%6,%7}, {%8,%9}, {%0,%1,%2,%3};" \
        : "+f"((d)[0]), "+f"((d)[1]), "+f"((d)[2]), "+f"((d)[3]) \
        : "r"((a)[0]), "r"((a)[1]), "r"((a)[2]), "r"((a)[3]), \
          "r"(bb0), "r"(bb1))

#define LDSM4(d0,d1,d2,d3,a) \
    asm volatile("ldmatrix.sync.aligned.m8n8.x4.shared.b16 {%0,%1,%2,%3}, [%4];" \
        : "=r"(d0), "=r"(d1), "=r"(d2), "=r"(d3) : "r"(a))
#define LDSM4T(d0,d1,d2,d3,a) \
    asm volatile("ldmatrix.sync.aligned.m8n8.x4.trans.shared.b16 {%0,%1,%2,%3}, [%4];" \
        : "=r"(d0), "=r"(d1), "=r"(d2), "=r"(d3) : "r"(a))

__device__ __forceinline__ uint32_t packf16(float lo, float hi) {
    uint32_t r;
    asm("cvt.rn.f16x2.f32 %0, %1, %2;" : "=r"(r) : "f"(hi), "f"(lo));
    return r;
}
__device__ __forceinline__ float f16_round(float x) {
    return __half2float(__float2half(x));
}

// ---------------------------------------------------------------------------
// fp32 -> fp16 convert (GEMM operands)
// ---------------------------------------------------------------------------
__global__ void to_f16(const float* __restrict__ X, __half* __restrict__ Y, int n4)
{
    int i = blockIdx.x * blockDim.x + threadIdx.x;
    if (i >= n4) return;
    float4 v = reinterpret_cast<const float4*>(X)[i];
    uint2 o;
    o.x = packf16(v.x, v.y);
    o.y = packf16(v.z, v.w);
    reinterpret_cast<uint2*>(Y)[i] = o;
}

// ---------------------------------------------------------------------------
// fp32 -> fp16 hi/lo split (V)
// ---------------------------------------------------------------------------
__global__ void split_f16(const float* __restrict__ X,
                          __half* __restrict__ Hh, __half* __restrict__ Ll, int n4)
{
    int i = blockIdx.x * blockDim.x + threadIdx.x;
    if (i >= n4) return;
    float4 v = reinterpret_cast<const float4*>(X)[i];
    __half h0 = __float2half(v.x), h1 = __float2half(v.y);
    __half h2 = __float2half(v.z), h3 = __float2half(v.w);
    __half l0 = __float2half(v.x - __half2float(h0));
    __half l1 = __float2half(v.y - __half2float(h1));
    __half l2 = __float2half(v.z - __half2float(h2));
    __half l3 = __float2half(v.w - __half2float(h3));
    ushort4 hp, lp;
    hp.x = __half_as_ushort(h0); hp.y = __half_as_ushort(h1);
    hp.z = __half_as_ushort(h2); hp.w = __half_as_ushort(h3);
    lp.x = __half_as_ushort(l0); lp.y = __half_as_ushort(l1);
    lp.z = __half_as_ushort(l2); lp.w = __half_as_ushort(l3);
    reinterpret_cast<ushort4*>(Hh)[i] = hp;
    reinterpret_cast<ushort4*>(Ll)[i] = lp;
}

// ---------------------------------------------------------------------------
// Fused RoPE (+scale) + fp16 convert (flash QK operands)
// ---------------------------------------------------------------------------
__global__ void rope_f16(const float* __restrict__ src, __half* __restrict__ dst,
                         const float* __restrict__ fc, const float* __restrict__ fs,
                         int heads, float sc)
{
    int idx = blockIdx.x * blockDim.x + threadIdx.x;
    int total = T_ * heads * (HD_/4);
    if (idx >= total) return;
    int i32 = idx & 31;
    int rem = idx >> 5;
    int h   = rem % heads;
    int t   = rem / heads;
    int s   = t & (S_ - 1);
    int p0  = 2 * i32;
    float c0 = fc[s*64 + p0],     s0 = fs[s*64 + p0];
    float c1 = fc[s*64 + p0 + 1], s1 = fs[s*64 + p0 + 1];
    size_t base = (size_t)t * heads * HD_ + h * HD_ + 4*i32;
    float4 v = *reinterpret_cast<const float4*>(src + base);
    uint2 o;
    o.x = packf16((v.x * c0 - v.y * s0) * sc, (v.x * s0 + v.y * c0) * sc);
    o.y = packf16((v.z * c1 - v.w * s1) * sc, (v.z * s1 + v.w * c1) * sc);
    *reinterpret_cast<uint2*>(dst + base) = o;
}

// ---------------------------------------------------------------------------
// fp16 single-pass GEMM (R11-winning config, unchanged)
// ---------------------------------------------------------------------------
#define GT_BYTES 16384
#define GSTAGE (2 * GT_BYTES)
#define GF16_SMEM (2 * GSTAGE)

__device__ __forceinline__ void g16_copy(
    uint32_t sbase, const __half* __restrict__ Ab, const __half* __restrict__ Bb,
    int K, int k0, int tid)
{
    #pragma unroll
    for (int t = 0; t < 2; t++) {
        const __half* src = t ? Bb : Ab;
        uint32_t toff = sbase + t * GT_BYTES;
        #pragma unroll
        for (int p = 0; p < 4; p++) {
            int idx = p * 256 + tid;
            int row = idx >> 3;
            int ch  = idx & 7;
            uint32_t dst = toff + row * 128 +
                           (uint32_t)((ch * 16) ^ ((row & 7) << 4));
            cp_async16(dst, src + (size_t)row * K + k0 + ch * 8);
        }
    }
}

__global__ void __launch_bounds__(256)
gemm_f16(const __half* __restrict__ A, const __half* __restrict__ Bw,
         float* __restrict__ C, int M, int N, int K)
{
    extern __shared__ __align__(1024) char smem[];
    const uint32_t sb0 = smem_to_u32(smem);
    const int tid  = threadIdx.x;
    const int wid  = tid >> 5;
    const int lane = tid & 31;
    const int bm = blockIdx.y * 128;
    const int bn = blockIdx.x * 128;
    const int warp_m = (wid >> 2) * 64;
    const int warp_n = (wid & 3) * 32;
    const int NC = K >> 6;

    const __half* Ab = A  + (size_t)bm * K;
    const __half* Bb = Bw + (size_t)bn * K;

    float acc[4][4][4];
    #pragma unroll
    for (int i = 0; i < 4; i++)
        #pragma unroll
        for (int j = 0; j < 4; j++)
            #pragma unroll
            for (int r = 0; r < 4; r++) acc[i][j][r] = 0.f;

    const int lg  = lane >> 2;
    const int lk4 = (lane & 3) * 4;

    g16_copy(sb0, Ab, Bb, K, 0, tid);
    CP_COMMIT();

    for (int c = 0; c < NC; c++) {
        if (c + 1 < NC) {
            g16_copy(sb0 + ((c + 1) & 1) * GSTAGE, Ab, Bb, K, (c + 1) << 6, tid);
            CP_COMMIT();
            CP_WAIT(1);
        } else {
            CP_WAIT(0);
        }
        __syncthreads();

        const uint32_t sb = sb0 + (c & 1) * GSTAGE;

        #pragma unroll
        for (int ks = 0; ks < 4; ks++) {
            const int kb = ks * 32 + lk4;

            uint32_t ah[4][4], bh[4][2];
            #pragma unroll
            for (int mt = 0; mt < 4; mt++) {
                int r0 = warp_m + mt * 16 + lg;
                int r1 = r0 + 8;
                uint32_t rb0 = r0 * 128, rx0 = (r0 & 7) << 4;
                uint32_t rb1 = r1 * 128, rx1 = (r1 & 7) << 4;
                ah[mt][0] = lds32(sb + rb0 + (kb ^ rx0));
                ah[mt][1] = lds32(sb + rb1 + (kb ^ rx1));
                ah[mt][2] = lds32(sb + rb0 + ((kb + 16) ^ rx0));
                ah[mt][3] = lds32(sb + rb1 + ((kb + 16) ^ rx1));
            }
            #pragma unroll
            for (int nt = 0; nt < 4; nt++) {
                int n = warp_n + nt * 8 + lg;
                uint32_t rb = n * 128, rx = (n & 7) << 4;
                bh[nt][0] = lds32(sb + GT_BYTES + rb + (kb ^ rx));
                bh[nt][1] = lds32(sb + GT_BYTES + rb + ((kb + 16) ^ rx));
            }
            #pragma unroll
            for (int mt = 0; mt < 4; mt++)
                #pragma unroll
                for (int nt = 0; nt < 4; nt++)
                    MMA_F16(acc[mt][nt], ah[mt], bh[nt][0], bh[nt][1]);
        }
        __syncthreads();
    }

    #pragma unroll
    for (int mt = 0; mt < 4; mt++) {
        int row = bm + warp_m + mt * 16 + lg;
        #pragma unroll
        for (int nt = 0; nt < 4; nt++) {
            int col = bn + warp_n + nt * 8 + (lane & 3) * 2;
            *(float2*)(C + (size_t)row * N + col) =
                make_float2(acc[mt][nt][0], acc[mt][nt][1]);
            *(float2*)(C + (size_t)(row + 8) * N + col) =
                make_float2(acc[mt][nt][2], acc[mt][nt][3]);
        }
    }
}

// ---------------------------------------------------------------------------
// Flash attention v12: QK^T fp16 single-pass (== tf32 precision, half the
// MMAs), PV fp16 3-term, deferred l-sum, fp16 epilogue.
// Smem: Q fp16 32KB + 2 stages x (K 16KB + Vh 16KB + Vl 16KB) = 128KB.
// ---------------------------------------------------------------------------
#define FQ12 (128 * 256)             // Q fp16
#define FK12 (64 * 256)              // K fp16
#define FV12 (64 * 256)              // V fp16 (per hi/lo)
#define FST12 (FK12 + 2 * FV12)      // 48KB per stage
#define FA12_SMEM (FQ12 + 2 * FST12) // 131072

__device__ __forceinline__ void fa12_load_kv(
    uint32_t sbase, const __half* __restrict__ K16,
    const __half* __restrict__ Vh, const __half* __restrict__ Vl,
    int tk0, int g, int tid)
{
    const __half* srcs[3] = {K16 + (size_t)tk0 * (KV_*HD_) + g * HD_,
                             Vh  + (size_t)tk0 * (KV_*HD_) + g * HD_,
                             Vl  + (size_t)tk0 * (KV_*HD_) + g * HD_};
    #pragma unroll
    for (int t = 0; t < 3; t++) {
        #pragma unroll
        for (int it = 0; it < 4; it++) {
            int idx = it * 256 + tid;
            int row = idx >> 4, ch = idx & 15;
            uint32_t dst = sbase + t * FK12 + row * 256 +
                           (uint32_t)((ch * 16) ^ ((row & 7) << 4));
            cp_async16(dst, srcs[t] + (size_t)row * (KV_*HD_) + ch * 8);
        }
    }
}

__global__ void __launch_bounds__(256, 1)
flash_v12(const __half* __restrict__ Q16, const __half* __restrict__ K16,
          const __half* __restrict__ Vh, const __half* __restrict__ Vl,
          __half* __restrict__ Og)
{
    extern __shared__ __align__(1024) char fsm[];
    const uint32_t sb = smem_to_u32(fsm);
    const int tid  = threadIdx.x;
    const int wid  = tid >> 5;
    const int lane = tid & 31;
    const int qt = (gridDim.x - 1) - blockIdx.x;   // heavy tiles first
    const int h  = blockIdx.y;
    const int b  = blockIdx.z;
    const int g  = h / REP_;
    const int q0 = qt * 128;
    const int t0 = b * S_ + q0;
    const int nt = 2 * qt + 2;

    const int l7    = lane & 7;
    const int lb8   = (lane >> 3) & 1;
    const int lhi16 = (lane >= 16) ? 16 : 0;
    // Q A-frag (fp16, R4-validated geometry)
    const int qrow  = 16 * wid + l7 + lb8 * 8;
    const uint32_t qswz = (uint32_t)(l7 << 4);
    // K B-frag (fp16 non-trans)
    const int krow_l = l7 + ((lane >= 16) ? 8 : 0);
    const int kgsel  = lb8 * 16;
    const uint32_t kswz = (uint32_t)(l7 << 4);
    // V B-frag (fp16 trans)
    const int vrow_l = l7 + lb8 * 8;
    const int vgsel  = lhi16;
    const uint32_t vswz = (uint32_t)(l7 << 4);

    fa12_load_kv(sb + FQ12, K16, Vh, Vl, b * S_, g, tid);
    CP_COMMIT();
    {   // stage Q (fp16, 128 rows x 256B)
        const __half* src = Q16 + (size_t)t0 * D_ + h * HD_;
        #pragma unroll
        for (int it = 0; it < 8; it++) {
            int idx = it * 256 + tid;
            int row = idx >> 4, ch = idx & 15;
            uint32_t dst = sb + row * 256 + (uint32_t)((ch * 16) ^ ((row & 7) << 4));
            cp_async16(dst, src + (size_t)row * D_ + ch * 8);
        }
        CP_COMMIT();
    }

    float o[16][4];
    #pragma unroll
    for (int f = 0; f < 16; f++)
        #pragma unroll
        for (int r = 0; r < 4; r++) o[f][r] = 0.f;
    float m0 = -1e30f, m1 = -1e30f;
    float lsum0 = 0.f, lsum1 = 0.f;

    const int r0g = q0 + 16 * wid + (lane >> 2);
    const int c0l = (lane & 3) * 2;

    for (int t = 0; t < nt; t++) {
        CP_WAIT(0);
        __syncthreads();
        if (t + 1 < nt) {
            fa12_load_kv(sb + FQ12 + ((t + 1) & 1) * FST12,
                         K16, Vh, Vl, b * S_ + (t + 1) * 64, g, tid);
            CP_COMMIT();
        }

        const uint32_t kb  = sb + FQ12 + (t & 1) * FST12;
        const uint32_t vhb = kb + FK12;

        float s[8][4];
        #pragma unroll
        for (int j = 0; j < 8; j++)
            #pragma unroll
            for (int r = 0; r < 4; r++) s[j][r] = 0.f;

        // ---- S = Q K^T (fp16 single pass; mantissa == tf32) ----
        #pragma unroll
        for (int kk = 0; kk < 8; kk++) {
            uint32_t qh[4];
            uint32_t qa = sb + qrow * 256 + (uint32_t)(((kk * 32) + lhi16) ^ qswz);
            LDSM4(qh[0], qh[1], qh[2], qh[3], qa);
            #pragma unroll
            for (int np = 0; np < 4; np++) {
                uint32_t ka = kb + (np * 16 + krow_l) * 256 +
                              (uint32_t)(((kk * 32) + kgsel) ^ kswz);
                uint32_t b0, b1, b2, b3;
                LDSM4(b0, b1, b2, b3, ka);
                MMA_F16(s[2*np],   qh, b0, b1);
                MMA_F16(s[2*np+1], qh, b2, b3);
            }
        }

        if (t >= 2 * qt) {   // diagonal tile: causal mask
            const int k0 = t * 64;
            #pragma unroll
            for (int j = 0; j < 8; j++) {
                int cg = k0 + 8 * j + c0l;
                if (cg     > r0g)     s[j][0] = -1e30f;
                if (cg + 1 > r0g)     s[j][1] = -1e30f;
                if (cg     > r0g + 8) s[j][2] = -1e30f;
                if (cg + 1 > r0g + 8) s[j][3] = -1e30f;
            }
        }

        // ---- online softmax ----
        float rm0 = -1e30f, rm1 = -1e30f;
        #pragma unroll
        for (int j = 0; j < 8; j++) {
            rm0 = fmaxf(rm0, fmaxf(s[j][0], s[j][1]));
            rm1 = fmaxf(rm1, fmaxf(s[j][2], s[j][3]));
        }
        rm0 = fmaxf(rm0, __shfl_xor_sync(0xffffffffu, rm0, 1));
        rm0 = fmaxf(rm0, __shfl_xor_sync(0xffffffffu, rm0, 2));
        rm1 = fmaxf(rm1, __shfl_xor_sync(0xffffffffu, rm1, 1));
        rm1 = fmaxf(rm1, __shfl_xor_sync(0xffffffffu, rm1, 2));
        float mn0 = fmaxf(m0, rm0), mn1 = fmaxf(m1, rm1);
        float a0 = __expf(m0 - mn0), a1 = __expf(m1 - mn1);
        m0 = mn0; m1 = mn1;
        float sum0 = 0.f, sum1 = 0.f;
        #pragma unroll
        for (int j = 0; j < 8; j++) {
            s[j][0] = __expf(s[j][0] - mn0);
            s[j][1] = __expf(s[j][1] - mn0);
            s[j][2] = __expf(s[j][2] - mn1);
            s[j][3] = __expf(s[j][3] - mn1);
            sum0 += s[j][0] + s[j][1];
            sum1 += s[j][2] + s[j][3];
        }
        lsum0 = lsum0 * a0 + sum0;
        lsum1 = lsum1 * a1 + sum1;
        #pragma unroll
        for (int f = 0; f < 16; f++) {
            o[f][0] *= a0; o[f][1] *= a0;
            o[f][2] *= a1; o[f][3] *= a1;
        }

        // ---- O += P V (fp16 3-term: PhVh + PlVh + PhVl) ----
        #pragma unroll
        for (int kk = 0; kk < 4; kk++) {
            uint32_t ah[4], al[4];
            float p00 = s[2*kk][0],   p01 = s[2*kk][1];
            float p02 = s[2*kk][2],   p03 = s[2*kk][3];
            float p10 = s[2*kk+1][0], p11 = s[2*kk+1][1];
            float p12 = s[2*kk+1][2], p13 = s[2*kk+1][3];
            ah[0] = packf16(p00, p01);
            ah[1] = packf16(p02, p03);
            ah[2] = packf16(p10, p11);
            ah[3] = packf16(p12, p13);
            al[0] = packf16(p00 - f16_round(p00), p01 - f16_round(p01));
            al[1] = packf16(p02 - f16_round(p02), p03 - f16_round(p03));
            al[2] = packf16(p10 - f16_round(p10), p11 - f16_round(p11));
            al[3] = packf16(p12 - f16_round(p12), p13 - f16_round(p13));
            #pragma unroll
            for (int dgp = 0; dgp < 8; dgp++) {
                uint32_t va = vhb + (kk * 16 + vrow_l) * 256 +
                              (uint32_t)(((dgp * 32) + vgsel) ^ vswz);
                uint32_t b0, b1, b2, b3, c0, c1, c2, c3;
                LDSM4T(b0, b1, b2, b3, va);
                LDSM4T(c0, c1, c2, c3, va + FV12);
                MMA_F16(o[2*dgp],   ah, b0, b1);
                MMA_F16(o[2*dgp],   al, b0, b1);
                MMA_F16(o[2*dgp],   ah, c0, c1);
                MMA_F16(o[2*dgp+1], ah, b2, b3);
                MMA_F16(o[2*dgp+1], al, b2, b3);
                MMA_F16(o[2*dgp+1], ah, c2, c3);
            }
        }
    }

    // epilogue: reduce l once, normalize, write fp16 (feeds fp16 O-proj)
    lsum0 += __shfl_xor_sync(0xffffffffu, lsum0, 1);
    lsum0 += __shfl_xor_sync(0xffffffffu, lsum0, 2);
    lsum1 += __shfl_xor_sync(0xffffffffu, lsum1, 1);
    lsum1 += __shfl_xor_sync(0xffffffffu, lsum1, 2);
    const float inv0 = 1.0f / lsum0;
    const float inv1 = 1.0f / lsum1;
    const int rowg = t0 + 16 * wid + (lane >> 2);
    #pragma unroll
    for (int dg = 0; dg < 16; dg++) {
        int col = h * HD_ + dg * 8 + (lane & 3) * 2;
        *reinterpret_cast<uint32_t*>(Og + (size_t)rowg * D_ + col) =
            packf16(o[dg][0] * inv0, o[dg][1] * inv0);
        *reinterpret_cast<uint32_t*>(Og + (size_t)(rowg + 8) * D_ + col) =
            packf16(o[dg][2] * inv1, o[dg][3] * inv1);
    }
}

// ---------------------------------------------------------------------------
extern "C" void kernel_launch(void* const* d_in, const int* in_sizes, int n_in,
                              void* d_out, int out_size)
{
    const float* x  = (const float*)d_in[0];
    const float* fc = (const float*)d_in[1];
    const float* fs = (const float*)d_in[2];
    const float* wq = (const float*)d_in[3];
    const float* wk = (const float*)d_in[4];
    const float* wv = (const float*)d_in[5];
    const float* wo = (const float*)d_in[6];
    float* out = (float*)d_out;

    float *qp, *kp, *vp;
    cudaGetSymbolAddress((void**)&qp, g_q);
    cudaGetSymbolAddress((void**)&kp, g_k);
    cudaGetSymbolAddress((void**)&vp, g_v);
    __half *x16, *wq16, *wk16, *wv16, *wo16, *attn16, *q16, *k16, *vh, *vl;
    cudaGetSymbolAddress((void**)&x16,  g_x16);
    cudaGetSymbolAddress((void**)&wq16, g_wq16);
    cudaGetSymbolAddress((void**)&wk16, g_wk16);
    cudaGetSymbolAddress((void**)&wv16, g_wv16);
    cudaGetSymbolAddress((void**)&wo16, g_wo16);
    cudaGetSymbolAddress((void**)&attn16, g_attn16);
    cudaGetSymbolAddress((void**)&q16, g_q16);
    cudaGetSymbolAddress((void**)&k16, g_k16);
    cudaGetSymbolAddress((void**)&vh, g_vh);
    cudaGetSymbolAddress((void**)&vl, g_vl);

    cudaFuncSetAttribute(gemm_f16,
                         cudaFuncAttributeMaxDynamicSharedMemorySize, GF16_SMEM);
    cudaFuncSetAttribute(flash_v12,
                         cudaFuncAttributeMaxDynamicSharedMemorySize, FA12_SMEM);

    const int n4_xd = T_ * D_ / 4;
    const int n4_w  = D_ * D_ / 4;
    const int n4_kv = KV_ * HD_ * D_ / 4;
    const int n4_kvt = T_ * KV_ * HD_ / 4;
    const float scale = 0.08838834764831845f;  // 1/sqrt(128)

    to_f16<<<(n4_xd + 255)/256, 256>>>(x,  x16,  n4_xd);
    to_f16<<<(n4_w  + 255)/256, 256>>>(wq, wq16, n4_w);
    to_f16<<<(n4_kv + 255)/256, 256>>>(wk, wk16, n4_kv);
    to_f16<<<(n4_kv + 255)/256, 256>>>(wv, wv16, n4_kv);
    to_f16<<<(n4_w  + 255)/256, 256>>>(wo, wo16, n4_w);

    dim3 blk(256);
    gemm_f16<<<dim3(D_/128, T_/128), blk, GF16_SMEM>>>(x16, wq16, qp, T_, D_, D_);
    gemm_f16<<<dim3((KV_*HD_)/128, T_/128), blk, GF16_SMEM>>>(x16, wk16, kp, T_, KV_*HD_, D_);
    gemm_f16<<<dim3((KV_*HD_)/128, T_/128), blk, GF16_SMEM>>>(x16, wv16, vp, T_, KV_*HD_, D_);

    rope_f16<<<(T_*H_*(HD_/4))/256,  256>>>(qp, q16, fc, fs, H_, scale);
    rope_f16<<<(T_*KV_*(HD_/4))/256, 256>>>(kp, k16, fc, fs, KV_, 1.0f);
    split_f16<<<(n4_kvt + 255)/256, 256>>>(vp, vh, vl, n4_kvt);

    flash_v12<<<dim3(S_/128, H_, B_), blk, FA12_SMEM>>>(q16, k16, vh, vl, attn16);

    gemm_f16<<<dim3(D_/128, T_/128), blk, GF16_SMEM>>>(attn16, wo16, out, T_, D_, D_);
}

// round 13
// speedup vs baseline: 2.5156x; 1.0026x over previous
#include <cuda_runtime.h>
#include <cuda_bf16.h>
#include <cuda_fp16.h>
#include <math.h>
#include <cstdint>

#define B_ 2
#define S_ 2048
#define D_ 4096
#define H_ 32
#define KV_ 8
#define HD_ 128
#define T_ (B_*S_)
#define REP_ (H_/KV_)

// ---------------------------------------------------------------------------
// Scratch (device globals: allocation-free rule)
// ---------------------------------------------------------------------------
__device__ float g_q[T_ * D_];             // Q proj (pre-rope fp32)
__device__ float g_k[T_ * KV_ * HD_];      // K proj (pre-rope fp32)
__device__ float g_v[T_ * KV_ * HD_];      // V proj fp32
__device__ __half g_attn16[T_ * D_];       // attention out (fp16, feeds O-proj)

__device__ __half g_x16[T_ * D_];          // fp16 GEMM operands
__device__ __half g_wq16[D_ * D_];
__device__ __half g_wk16[KV_ * HD_ * D_];
__device__ __half g_wv16[KV_ * HD_ * D_];
__device__ __half g_wo16[D_ * D_];

__device__ __half g_q16[T_ * D_];          // roped+scaled fp16 Q
__device__ __half g_k16[T_ * KV_ * HD_];   // roped fp16 K
__device__ __half g_vh[T_ * KV_ * HD_];    // V fp16 hi
__device__ __half g_vl[T_ * KV_ * HD_];    // V fp16 lo

// ---------------------------------------------------------------------------
// Helpers
// ---------------------------------------------------------------------------
__device__ __forceinline__ uint32_t smem_to_u32(const void* smem_ptr) {
    uint32_t addr;
    asm("{ .reg .u64 tmp; cvta.to.shared.u64 tmp, %1; cvt.u32.u64 %0, tmp; }"
        : "=r"(addr) : "l"(smem_ptr));
    return addr;
}
__device__ __forceinline__ void cp_async16(uint32_t saddr, const void* gaddr) {
    asm volatile("cp.async.cg.shared.global [%0], [%1], 16;"
                 :: "r"(saddr), "l"(gaddr));
}
#define CP_COMMIT() asm volatile("cp.async.commit_group;")
#define CP_WAIT(n)  asm volatile("cp.async.wait_group %0;" :: "n"(n))

__device__ __forceinline__ uint32_t lds32(uint32_t addr) {
    uint32_t v;
    asm("ld.shared.b32 %0, [%1];" : "=r"(v) : "r"(addr));
    return v;
}

#define MMA_F16(d, a, bb0, bb1) \
    asm volatile("mma.sync.aligned.m16n8k16.row.col.f32.f16.f16.f32 " \
        "{%0,%1,%2,%3}, {%4,%5,%6,%7}, {%8,%9}, {%0,%1,%2,%3};" \
        : "+f"((d)[0]), "+f"((d)[1]), "+f"((d)[2]), "+f"((d)[3]) \
        : "r"((a)[0]), "r"((a)[1]), "r"((a)[2]), "r"((a)[3]), \
          "r"(bb0), "r"(bb1))

#define LDSM4(d0,d1,d2,d3,a) \
    asm volatile("ldmatrix.sync.aligned.m8n8.x4.shared.b16 {%0,%1,%2,%3}, [%4];" \
        : "=r"(d0), "=r"(d1), "=r"(d2), "=r"(d3) : "r"(a))
#define LDSM4T(d0,d1,d2,d3,a) \
    asm volatile("ldmatrix.sync.aligned.m8n8.x4.trans.shared.b16 {%0,%1,%2,%3}, [%4];" \
        : "=r"(d0), "=r"(d1), "=r"(d2), "=r"(d3) : "r"(a))

__device__ __forceinline__ uint32_t packf16(float lo, float hi) {
    uint32_t r;
    asm("cvt.rn.f16x2.f32 %0, %1, %2;" : "=r"(r) : "f"(hi), "f"(lo));
    return r;
}
__device__ __forceinline__ float f16_round(float x) {
    return __half2float(__float2half(x));
}

// ---------------------------------------------------------------------------
// fp32 -> fp16 convert (GEMM operands)
// ---------------------------------------------------------------------------
__global__ void to_f16(const float* __restrict__ X, __half* __restrict__ Y, int n4)
{
    int i = blockIdx.x * blockDim.x + threadIdx.x;
    if (i >= n4) return;
    float4 v = reinterpret_cast<const float4*>(X)[i];
    uint2 o;
    o.x = packf16(v.x, v.y);
    o.y = packf16(v.z, v.w);
    reinterpret_cast<uint2*>(Y)[i] = o;
}

// ---------------------------------------------------------------------------
// fp32 -> fp16 hi/lo split (V)
// ---------------------------------------------------------------------------
__global__ void split_f16(const float* __restrict__ X,
                          __half* __restrict__ Hh, __half* __restrict__ Ll, int n4)
{
    int i = blockIdx.x * blockDim.x + threadIdx.x;
    if (i >= n4) return;
    float4 v = reinterpret_cast<const float4*>(X)[i];
    __half h0 = __float2half(v.x), h1 = __float2half(v.y);
    __half h2 = __float2half(v.z), h3 = __float2half(v.w);
    __half l0 = __float2half(v.x - __half2float(h0));
    __half l1 = __float2half(v.y - __half2float(h1));
    __half l2 = __float2half(v.z - __half2float(h2));
    __half l3 = __float2half(v.w - __half2float(h3));
    ushort4 hp, lp;
    hp.x = __half_as_ushort(h0); hp.y = __half_as_ushort(h1);
    hp.z = __half_as_ushort(h2); hp.w = __half_as_ushort(h3);
    lp.x = __half_as_ushort(l0); lp.y = __half_as_ushort(l1);
    lp.z = __half_as_ushort(l2); lp.w = __half_as_ushort(l3);
    reinterpret_cast<ushort4*>(Hh)[i] = hp;
    reinterpret_cast<ushort4*>(Ll)[i] = lp;
}

// ---------------------------------------------------------------------------
// Fused RoPE (+scale) + fp16 convert (flash QK operands)
// ---------------------------------------------------------------------------
__global__ void rope_f16(const float* __restrict__ src, __half* __restrict__ dst,
                         const float* __restrict__ fc, const float* __restrict__ fs,
                         int heads, float sc)
{
    int idx = blockIdx.x * blockDim.x + threadIdx.x;
    int total = T_ * heads * (HD_/4);
    if (idx >= total) return;
    int i32 = idx & 31;
    int rem = idx >> 5;
    int h   = rem % heads;
    int t   = rem / heads;
    int s   = t & (S_ - 1);
    int p0  = 2 * i32;
    float c0 = fc[s*64 + p0],     s0 = fs[s*64 + p0];
    float c1 = fc[s*64 + p0 + 1], s1 = fs[s*64 + p0 + 1];
    size_t base = (size_t)t * heads * HD_ + h * HD_ + 4*i32;
    float4 v = *reinterpret_cast<const float4*>(src + base);
    uint2 o;
    o.x = packf16((v.x * c0 - v.y * s0) * sc, (v.x * s0 + v.y * c0) * sc);
    o.y = packf16((v.z * c1 - v.w * s1) * sc, (v.z * s1 + v.w * c1) * sc);
    *reinterpret_cast<uint2*>(dst + base) = o;
}

// ---------------------------------------------------------------------------
// fp16 single-pass GEMM (R11-winning body) + blockIdx.z weight/output select
// ---------------------------------------------------------------------------
#define GT_BYTES 16384
#define GSTAGE (2 * GT_BYTES)
#define GF16_SMEM (2 * GSTAGE)

__device__ __forceinline__ void g16_copy(
    uint32_t sbase, const __half* __restrict__ Ab, const __half* __restrict__ Bb,
    int K, int k0, int tid)
{
    #pragma unroll
    for (int t = 0; t < 2; t++) {
        const __half* src = t ? Bb : Ab;
        uint32_t toff = sbase + t * GT_BYTES;
        #pragma unroll
        for (int p = 0; p < 4; p++) {
            int idx = p * 256 + tid;
            int row = idx >> 3;
            int ch  = idx & 7;
            uint32_t dst = toff + row * 128 +
                           (uint32_t)((ch * 16) ^ ((row & 7) << 4));
            cp_async16(dst, src + (size_t)row * K + k0 + ch * 8);
        }
    }
}

__global__ void __launch_bounds__(256)
gemm_f16(const __half* __restrict__ A,
         const __half* __restrict__ B0, const __half* __restrict__ B1,
         float* __restrict__ C0, float* __restrict__ C1,
         int N, int K)
{
    extern __shared__ __align__(1024) char smem[];
    const uint32_t sb0 = smem_to_u32(smem);
    const int tid  = threadIdx.x;
    const int wid  = tid >> 5;
    const int lane = tid & 31;
    const int bm = blockIdx.y * 128;
    const int bn = blockIdx.x * 128;
    const __half* Bw = blockIdx.z ? B1 : B0;
    float* C = blockIdx.z ? C1 : C0;
    const int warp_m = (wid >> 2) * 64;
    const int warp_n = (wid & 3) * 32;
    const int NC = K >> 6;

    const __half* Ab = A  + (size_t)bm * K;
    const __half* Bb = Bw + (size_t)bn * K;

    float acc[4][4][4];
    #pragma unroll
    for (int i = 0; i < 4; i++)
        #pragma unroll
        for (int j = 0; j < 4; j++)
            #pragma unroll
            for (int r = 0; r < 4; r++) acc[i][j][r] = 0.f;

    const int lg  = lane >> 2;
    const int lk4 = (lane & 3) * 4;

    g16_copy(sb0, Ab, Bb, K, 0, tid);
    CP_COMMIT();

    for (int c = 0; c < NC; c++) {
        if (c + 1 < NC) {
            g16_copy(sb0 + ((c + 1) & 1) * GSTAGE, Ab, Bb, K, (c + 1) << 6, tid);
            CP_COMMIT();
            CP_WAIT(1);
        } else {
            CP_WAIT(0);
        }
        __syncthreads();

        const uint32_t sb = sb0 + (c & 1) * GSTAGE;

        #pragma unroll
        for (int ks = 0; ks < 4; ks++) {
            const int kb = ks * 32 + lk4;

            uint32_t ah[4][4], bh[4][2];
            #pragma unroll
            for (int mt = 0; mt < 4; mt++) {
                int r0 = warp_m + mt * 16 + lg;
                int r1 = r0 + 8;
                uint32_t rb0 = r0 * 128, rx0 = (r0 & 7) << 4;
                uint32_t rb1 = r1 * 128, rx1 = (r1 & 7) << 4;
                ah[mt][0] = lds32(sb + rb0 + (kb ^ rx0));
                ah[mt][1] = lds32(sb + rb1 + (kb ^ rx1));
                ah[mt][2] = lds32(sb + rb0 + ((kb + 16) ^ rx0));
                ah[mt][3] = lds32(sb + rb1 + ((kb + 16) ^ rx1));
            }
            #pragma unroll
            for (int nt = 0; nt < 4; nt++) {
                int n = warp_n + nt * 8 + lg;
                uint32_t rb = n * 128, rx = (n & 7) << 4;
                bh[nt][0] = lds32(sb + GT_BYTES + rb + (kb ^ rx));
                bh[nt][1] = lds32(sb + GT_BYTES + rb + ((kb + 16) ^ rx));
            }
            #pragma unroll
            for (int mt = 0; mt < 4; mt++)
                #pragma unroll
                for (int nt = 0; nt < 4; nt++)
                    MMA_F16(acc[mt][nt], ah[mt], bh[nt][0], bh[nt][1]);
        }
        __syncthreads();
    }

    #pragma unroll
    for (int mt = 0; mt < 4; mt++) {
        int row = bm + warp_m + mt * 16 + lg;
        #pragma unroll
        for (int nt = 0; nt < 4; nt++) {
            int col = bn + warp_n + nt * 8 + (lane & 3) * 2;
            *(float2*)(C + (size_t)row * N + col) =
                make_float2(acc[mt][nt][0], acc[mt][nt][1]);
            *(float2*)(C + (size_t)(row + 8) * N + col) =
                make_float2(acc[mt][nt][2], acc[mt][nt][3]);
        }
    }
}

// ---------------------------------------------------------------------------
// Flash attention v13: K-tile 128 (halves per-key softmax/barrier overhead).
// QK^T fp16 single-pass, PV fp16 3-term, deferred l-sum, fp16 epilogue.
// Smem: Q 32KB + 2 stages x (K 32 + Vh 32 + Vl 32) = 224KB.
// ---------------------------------------------------------------------------
#define FQ13 (128 * 256)              // Q fp16
#define FK13 (128 * 256)              // K fp16 (128 keys)
#define FV13 (128 * 256)              // V fp16 per hi/lo
#define FST13 (FK13 + 2 * FV13)       // 96KB per stage
#define FA13_SMEM (FQ13 + 2 * FST13)  // 229376

__device__ __forceinline__ void fa13_load_kv(
    uint32_t sbase, const __half* __restrict__ K16,
    const __half* __restrict__ Vh, const __half* __restrict__ Vl,
    int tk0, int g, int tid)
{
    const __half* srcs[3] = {K16 + (size_t)tk0 * (KV_*HD_) + g * HD_,
                             Vh  + (size_t)tk0 * (KV_*HD_) + g * HD_,
                             Vl  + (size_t)tk0 * (KV_*HD_) + g * HD_};
    #pragma unroll
    for (int t = 0; t < 3; t++) {
        #pragma unroll
        for (int it = 0; it < 8; it++) {
            int idx = it * 256 + tid;
            int row = idx >> 4, ch = idx & 15;
            uint32_t dst = sbase + t * FK13 + row * 256 +
                           (uint32_t)((ch * 16) ^ ((row & 7) << 4));
            cp_async16(dst, srcs[t] + (size_t)row * (KV_*HD_) + ch * 8);
        }
    }
}

__global__ void __launch_bounds__(256, 1)
flash_v13(const __half* __restrict__ Q16, const __half* __restrict__ K16,
          const __half* __restrict__ Vh, const __half* __restrict__ Vl,
          __half* __restrict__ Og)
{
    extern __shared__ __align__(1024) char fsm[];
    const uint32_t sb = smem_to_u32(fsm);
    const int tid  = threadIdx.x;
    const int wid  = tid >> 5;
    const int lane = tid & 31;
    const int qt = (gridDim.x - 1) - blockIdx.x;   // heavy tiles first
    const int h  = blockIdx.y;
    const int b  = blockIdx.z;
    const int g  = h / REP_;
    const int q0 = qt * 128;
    const int t0 = b * S_ + q0;
    const int nt = qt + 1;                         // 128-key tiles

    const int l7    = lane & 7;
    const int lb8   = (lane >> 3) & 1;
    const int lhi16 = (lane >= 16) ? 16 : 0;
    const int qrow  = 16 * wid + l7 + lb8 * 8;
    const uint32_t qswz = (uint32_t)(l7 << 4);
    const int krow_l = l7 + ((lane >= 16) ? 8 : 0);
    const int kgsel  = lb8 * 16;
    const uint32_t kswz = (uint32_t)(l7 << 4);
    const int vrow_l = l7 + lb8 * 8;
    const int vgsel  = lhi16;
    const uint32_t vswz = (uint32_t)(l7 << 4);

    fa13_load_kv(sb + FQ13, K16, Vh, Vl, b * S_, g, tid);
    CP_COMMIT();
    {   // stage Q (fp16, 128 rows x 256B)
        const __half* src = Q16 + (size_t)t0 * D_ + h * HD_;
        #pragma unroll
        for (int it = 0; it < 8; it++) {
            int idx = it * 256 + tid;
            int row = idx >> 4, ch = idx & 15;
            uint32_t dst = sb + row * 256 + (uint32_t)((ch * 16) ^ ((row & 7) << 4));
            cp_async16(dst, src + (size_t)row * D_ + ch * 8);
        }
        CP_COMMIT();
    }

    float o[16][4];
    #pragma unroll
    for (int f = 0; f < 16; f++)
        #pragma unroll
        for (int r = 0; r < 4; r++) o[f][r] = 0.f;
    float m0 = -1e30f, m1 = -1e30f;
    float lsum0 = 0.f, lsum1 = 0.f;

    const int r0g = q0 + 16 * wid + (lane >> 2);
    const int c0l = (lane & 3) * 2;

    for (int t = 0; t < nt; t++) {
        CP_WAIT(0);
        __syncthreads();
        if (t + 1 < nt) {
            fa13_load_kv(sb + FQ13 + ((t + 1) & 1) * FST13,
                         K16, Vh, Vl, b * S_ + (t + 1) * 128, g, tid);
            CP_COMMIT();
        }

        const uint32_t kb  = sb + FQ13 + (t & 1) * FST13;
        const uint32_t vhb = kb + FK13;

        float s[16][4];
        #pragma unroll
        for (int j = 0; j < 16; j++)
            #pragma unroll
            for (int r = 0; r < 4; r++) s[j][r] = 0.f;

        // ---- S = Q K^T (fp16 single pass, 128 keys) ----
        #pragma unroll
        for (int kk = 0; kk < 8; kk++) {
            uint32_t qh[4];
            uint32_t qa = sb + qrow * 256 + (uint32_t)(((kk * 32) + lhi16) ^ qswz);
            LDSM4(qh[0], qh[1], qh[2], qh[3], qa);
            #pragma unroll
            for (int np = 0; np < 8; np++) {
                uint32_t ka = kb + (np * 16 + krow_l) * 256 +
                              (uint32_t)(((kk * 32) + kgsel) ^ kswz);
                uint32_t b0, b1, b2, b3;
                LDSM4(b0, b1, b2, b3, ka);
                MMA_F16(s[2*np],   qh, b0, b1);
                MMA_F16(s[2*np+1], qh, b2, b3);
            }
        }

        if (t == qt) {   // diagonal tile: causal mask
            const int k0 = t * 128;
            #pragma unroll
            for (int j = 0; j < 16; j++) {
                int cg = k0 + 8 * j + c0l;
                if (cg     > r0g)     s[j][0] = -1e30f;
                if (cg + 1 > r0g)     s[j][1] = -1e30f;
                if (cg     > r0g + 8) s[j][2] = -1e30f;
                if (cg + 1 > r0g + 8) s[j][3] = -1e30f;
            }
        }

        // ---- online softmax ----
        float rm0 = -1e30f, rm1 = -1e30f;
        #pragma unroll
        for (int j = 0; j < 16; j++) {
            rm0 = fmaxf(rm0, fmaxf(s[j][0], s[j][1]));
            rm1 = fmaxf(rm1, fmaxf(s[j][2], s[j][3]));
        }
        rm0 = fmaxf(rm0, __shfl_xor_sync(0xffffffffu, rm0, 1));
        rm0 = fmaxf(rm0, __shfl_xor_sync(0xffffffffu, rm0, 2));
        rm1 = fmaxf(rm1, __shfl_xor_sync(0xffffffffu, rm1, 1));
        rm1 = fmaxf(rm1, __shfl_xor_sync(0xffffffffu, rm1, 2));
        float mn0 = fmaxf(m0, rm0), mn1 = fmaxf(m1, rm1);
        float a0 = __expf(m0 - mn0), a1 = __expf(m1 - mn1);
        m0 = mn0; m1 = mn1;
        float sum0 = 0.f, sum1 = 0.f;
        #pragma unroll
        for (int j = 0; j < 16; j++) {
            s[j][0] = __expf(s[j][0] - mn0);
            s[j][1] = __expf(s[j][1] - mn0);
            s[j][2] = __expf(s[j][2] - mn1);
            s[j][3] = __expf(s[j][3] - mn1);
            sum0 += s[j][0] + s[j][1];
            sum1 += s[j][2] + s[j][3];
        }
        lsum0 = lsum0 * a0 + sum0;
        lsum1 = lsum1 * a1 + sum1;
        #pragma unroll
        for (int f = 0; f < 16; f++) {
            o[f][0] *= a0; o[f][1] *= a0;
            o[f][2] *= a1; o[f][3] *= a1;
        }

        // ---- O += P V (fp16 3-term: PhVh + PlVh + PhVl) ----
        #pragma unroll
        for (int kk = 0; kk < 8; kk++) {
            uint32_t ah[4], al[4];
            float p00 = s[2*kk][0],   p01 = s[2*kk][1];
            float p02 = s[2*kk][2],   p03 = s[2*kk][3];
            float p10 = s[2*kk+1][0], p11 = s[2*kk+1][1];
            float p12 = s[2*kk+1][2], p13 = s[2*kk+1][3];
            ah[0] = packf16(p00, p01);
            ah[1] = packf16(p02, p03);
            ah[2] = packf16(p10, p11);
            ah[3] = packf16(p12, p13);
            al[0] = packf16(p00 - f16_round(p00), p01 - f16_round(p01));
            al[1] = packf16(p02 - f16_round(p02), p03 - f16_round(p03));
            al[2] = packf16(p10 - f16_round(p10), p11 - f16_round(p11));
            al[3] = packf16(p12 - f16_round(p12), p13 - f16_round(p13));
            #pragma unroll
            for (int dgp = 0; dgp < 8; dgp++) {
                uint32_t va = vhb + (kk * 16 + vrow_l) * 256 +
                              (uint32_t)(((dgp * 32) + vgsel) ^ vswz);
                uint32_t b0, b1, b2, b3, c0, c1, c2, c3;
                LDSM4T(b0, b1, b2, b3, va);
                LDSM4T(c0, c1, c2, c3, va + FV13);
                MMA_F16(o[2*dgp],   ah, b0, b1);
                MMA_F16(o[2*dgp],   al, b0, b1);
                MMA_F16(o[2*dgp],   ah, c0, c1);
                MMA_F16(o[2*dgp+1], ah, b2, b3);
                MMA_F16(o[2*dgp+1], al, b2, b3);
                MMA_F16(o[2*dgp+1], ah, c2, c3);
            }
        }
    }

    // epilogue: reduce l once, normalize, write fp16 (feeds fp16 O-proj)
    lsum0 += __shfl_xor_sync(0xffffffffu, lsum0, 1);
    lsum0 += __shfl_xor_sync(0xffffffffu, lsum0, 2);
    lsum1 += __shfl_xor_sync(0xffffffffu, lsum1, 1);
    lsum1 += __shfl_xor_sync(0xffffffffu, lsum1, 2);
    const float inv0 = 1.0f / lsum0;
    const float inv1 = 1.0f / lsum1;
    const int rowg = t0 + 16 * wid + (lane >> 2);
    #pragma unroll
    for (int dg = 0; dg < 16; dg++) {
        int col = h * HD_ + dg * 8 + (lane & 3) * 2;
        *reinterpret_cast<uint32_t*>(Og + (size_t)rowg * D_ + col) =
            packf16(o[dg][0] * inv0, o[dg][1] * inv0);
        *reinterpret_cast<uint32_t*>(Og + (size_t)(rowg + 8) * D_ + col) =
            packf16(o[dg][2] * inv1, o[dg][3] * inv1);
    }
}

// ---------------------------------------------------------------------------
extern "C" void kernel_launch(void* const* d_in, const int* in_sizes, int n_in,
                              void* d_out, int out_size)
{
    const float* x  = (const float*)d_in[0];
    const float* fc = (const float*)d_in[1];
    const float* fs = (const float*)d_in[2];
    const float* wq = (const float*)d_in[3];
    const float* wk = (const float*)d_in[4];
    const float* wv = (const float*)d_in[5];
    const float* wo = (const float*)d_in[6];
    float* out = (float*)d_out;

    float *qp, *kp, *vp;
    cudaGetSymbolAddress((void**)&qp, g_q);
    cudaGetSymbolAddress((void**)&kp, g_k);
    cudaGetSymbolAddress((void**)&vp, g_v);
    __half *x16, *wq16, *wk16, *wv16, *wo16, *attn16, *q16, *k16, *vh, *vl;
    cudaGetSymbolAddress((void**)&x16,  g_x16);
    cudaGetSymbolAddress((void**)&wq16, g_wq16);
    cudaGetSymbolAddress((void**)&wk16, g_wk16);
    cudaGetSymbolAddress((void**)&wv16, g_wv16);
    cudaGetSymbolAddress((void**)&wo16, g_wo16);
    cudaGetSymbolAddress((void**)&attn16, g_attn16);
    cudaGetSymbolAddress((void**)&q16, g_q16);
    cudaGetSymbolAddress((void**)&k16, g_k16);
    cudaGetSymbolAddress((void**)&vh, g_vh);
    cudaGetSymbolAddress((void**)&vl, g_vl);

    cudaFuncSetAttribute(gemm_f16,
                         cudaFuncAttributeMaxDynamicSharedMemorySize, GF16_SMEM);
    cudaFuncSetAttribute(flash_v13,
                         cudaFuncAttributeMaxDynamicSharedMemorySize, FA13_SMEM);

    const int n4_xd = T_ * D_ / 4;
    const int n4_w  = D_ * D_ / 4;
    const int n4_kv = KV_ * HD_ * D_ / 4;
    const int n4_kvt = T_ * KV_ * HD_ / 4;
    const float scale = 0.08838834764831845f;  // 1/sqrt(128)

    to_f16<<<(n4_xd + 255)/256, 256>>>(x,  x16,  n4_xd);
    to_f16<<<(n4_w  + 255)/256, 256>>>(wq, wq16, n4_w);
    to_f16<<<(n4_kv + 255)/256, 256>>>(wk, wk16, n4_kv);
    to_f16<<<(n4_kv + 255)/256, 256>>>(wv, wv16, n4_kv);
    to_f16<<<(n4_w  + 255)/256, 256>>>(wo, wo16, n4_w);

    dim3 blk(256);
    // Q projection
    gemm_f16<<<dim3(D_/128, T_/128, 1), blk, GF16_SMEM>>>(
        x16, wq16, wq16, qp, qp, D_, D_);
    // fused K+V projections (z selects weight/output)
    gemm_f16<<<dim3((KV_*HD_)/128, T_/128, 2), blk, GF16_SMEM>>>(
        x16, wk16, wv16, kp, vp, KV_*HD_, D_);

    rope_f16<<<(T_*H_*(HD_/4))/256,  256>>>(qp, q16, fc, fs, H_, scale);
    rope_f16<<<(T_*KV_*(HD_/4))/256, 256>>>(kp, k16, fc, fs, KV_, 1.0f);
    split_f16<<<(n4_kvt + 255)/256, 256>>>(vp, vh, vl, n4_kvt);

    flash_v13<<<dim3(S_/128, H_, B_), blk, FA13_SMEM>>>(q16, k16, vh, vl, attn16);

    // O projection
    gemm_f16<<<dim3(D_/128, T_/128, 1), blk, GF16_SMEM>>>(
        attn16, wo16, wo16, out, out, D_, D_);
}

// round 14
// speedup vs baseline: 2.8253x; 1.1231x over previous
#include <cuda_runtime.h>
#include <cuda_bf16.h>
#include <cuda_fp16.h>
#include <math.h>
#include <cstdint>

#define B_ 2
#define S_ 2048
#define D_ 4096
#define H_ 32
#define KV_ 8
#define HD_ 128
#define T_ (B_*S_)
#define REP_ (H_/KV_)

// ---------------------------------------------------------------------------
// Scratch (device globals: allocation-free rule)
// ---------------------------------------------------------------------------
__device__ float g_q[T_ * D_];             // Q proj (pre-rope fp32)
__device__ float g_k[T_ * KV_ * HD_];      // K proj (pre-rope fp32)
__device__ float g_v[T_ * KV_ * HD_];      // V proj fp32
__device__ __half g_attn16[T_ * D_];       // attention out (fp16, feeds O-proj)

__device__ __half g_x16[T_ * D_];          // fp16 GEMM operands
__device__ __half g_wq16[D_ * D_];
__device__ __half g_wk16[KV_ * HD_ * D_];
__device__ __half g_wv16[KV_ * HD_ * D_];
__device__ __half g_wo16[D_ * D_];

__device__ __half g_q16[T_ * D_];          // roped+scaled fp16 Q
__device__ __half g_k16[T_ * KV_ * HD_];   // roped fp16 K
__device__ __half g_v16[T_ * KV_ * HD_];   // V fp16 (single-term)

// ---------------------------------------------------------------------------
// Helpers
// ---------------------------------------------------------------------------
__device__ __forceinline__ uint32_t smem_to_u32(const void* smem_ptr) {
    uint32_t addr;
    asm("{ .reg .u64 tmp; cvta.to.shared.u64 tmp, %1; cvt.u32.u64 %0, tmp; }"
        : "=r"(addr) : "l"(smem_ptr));
    return addr;
}
__device__ __forceinline__ void cp_async16(uint32_t saddr, const void* gaddr) {
    asm volatile("cp.async.cg.shared.global [%0], [%1], 16;"
                 :: "r"(saddr), "l"(gaddr));
}
#define CP_COMMIT() asm volatile("cp.async.commit_group;")
#define CP_WAIT(n)  asm volatile("cp.async.wait_group %0;" :: "n"(n))

__device__ __forceinline__ uint32_t lds32(uint32_t addr) {
    uint32_t v;
    asm("ld.shared.b32 %0, [%1];" : "=r"(v) : "r"(addr));
    return v;
}

#define MMA_F16(d, a, bb0, bb1) \
    asm volatile("mma.sync.aligned.m16n8k16.row.col.f32.f16.f16.f32 " \
        "{%0,%1,%2,%3}, {%4,%5,%6,%7}, {%8,%9}, {%0,%1,%2,%3};" \
        : "+f"((d)[0]), "+f"((d)[1]), "+f"((d)[2]), "+f"((d)[3]) \
        : "r"((a)[0]), "r"((a)[1]), "r"((a)[2]), "r"((a)[3]), \
          "r"(bb0), "r"(bb1))

#define LDSM4(d0,d1,d2,d3,a) \
    asm volatile("ldmatrix.sync.aligned.m8n8.x4.shared.b16 {%0,%1,%2,%3}, [%4];" \
        : "=r"(d0), "=r"(d1), "=r"(d2), "=r"(d3) : "r"(a))
#define LDSM4T(d0,d1,d2,d3,a) \
    asm volatile("ldmatrix.sync.aligned.m8n8.x4.trans.shared.b16 {%0,%1,%2,%3}, [%4];" \
        : "=r"(d0), "=r"(d1), "=r"(d2), "=r"(d3) : "r"(a))

__device__ __forceinline__ uint32_t packf16(float lo, float hi) {
    uint32_t r;
    asm("cvt.rn.f16x2.f32 %0, %1, %2;" : "=r"(r) : "f"(hi), "f"(lo));
    return r;
}

// ---------------------------------------------------------------------------
// fp32 -> fp16 convert
// ---------------------------------------------------------------------------
__global__ void to_f16(const float* __restrict__ X, __half* __restrict__ Y, int n4)
{
    int i = blockIdx.x * blockDim.x + threadIdx.x;
    if (i >= n4) return;
    float4 v = reinterpret_cast<const float4*>(X)[i];
    uint2 o;
    o.x = packf16(v.x, v.y);
    o.y = packf16(v.z, v.w);
    reinterpret_cast<uint2*>(Y)[i] = o;
}

// ---------------------------------------------------------------------------
// Fused RoPE (+scale) + fp16 convert (flash QK operands)
// ---------------------------------------------------------------------------
__global__ void rope_f16(const float* __restrict__ src, __half* __restrict__ dst,
                         const float* __restrict__ fc, const float* __restrict__ fs,
                         int heads, float sc)
{
    int idx = blockIdx.x * blockDim.x + threadIdx.x;
    int total = T_ * heads * (HD_/4);
    if (idx >= total) return;
    int i32 = idx & 31;
    int rem = idx >> 5;
    int h   = rem % heads;
    int t   = rem / heads;
    int s   = t & (S_ - 1);
    int p0  = 2 * i32;
    float c0 = fc[s*64 + p0],     s0 = fs[s*64 + p0];
    float c1 = fc[s*64 + p0 + 1], s1 = fs[s*64 + p0 + 1];
    size_t base = (size_t)t * heads * HD_ + h * HD_ + 4*i32;
    float4 v = *reinterpret_cast<const float4*>(src + base);
    uint2 o;
    o.x = packf16((v.x * c0 - v.y * s0) * sc, (v.x * s0 + v.y * c0) * sc);
    o.y = packf16((v.z * c1 - v.w * s1) * sc, (v.z * s1 + v.w * c1) * sc);
    *reinterpret_cast<uint2*>(dst + base) = o;
}

// ---------------------------------------------------------------------------
// fp16 single-pass GEMM (R11-winning body) + blockIdx.z weight/output select
// ---------------------------------------------------------------------------
#define GT_BYTES 16384
#define GSTAGE (2 * GT_BYTES)
#define GF16_SMEM (2 * GSTAGE)

__device__ __forceinline__ void g16_copy(
    uint32_t sbase, const __half* __restrict__ Ab, const __half* __restrict__ Bb,
    int K, int k0, int tid)
{
    #pragma unroll
    for (int t = 0; t < 2; t++) {
        const __half* src = t ? Bb : Ab;
        uint32_t toff = sbase + t * GT_BYTES;
        #pragma unroll
        for (int p = 0; p < 4; p++) {
            int idx = p * 256 + tid;
            int row = idx >> 3;
            int ch  = idx & 7;
            uint32_t dst = toff + row * 128 +
                           (uint32_t)((ch * 16) ^ ((row & 7) << 4));
            cp_async16(dst, src + (size_t)row * K + k0 + ch * 8);
        }
    }
}

__global__ void __launch_bounds__(256)
gemm_f16(const __half* __restrict__ A,
         const __half* __restrict__ B0, const __half* __restrict__ B1,
         float* __restrict__ C0, float* __restrict__ C1,
         int N, int K)
{
    extern __shared__ __align__(1024) char smem[];
    const uint32_t sb0 = smem_to_u32(smem);
    const int tid  = threadIdx.x;
    const int wid  = tid >> 5;
    const int lane = tid & 31;
    const int bm = blockIdx.y * 128;
    const int bn = blockIdx.x * 128;
    const __half* Bw = blockIdx.z ? B1 : B0;
    float* C = blockIdx.z ? C1 : C0;
    const int warp_m = (wid >> 2) * 64;
    const int warp_n = (wid & 3) * 32;
    const int NC = K >> 6;

    const __half* Ab = A  + (size_t)bm * K;
    const __half* Bb = Bw + (size_t)bn * K;

    float acc[4][4][4];
    #pragma unroll
    for (int i = 0; i < 4; i++)
        #pragma unroll
        for (int j = 0; j < 4; j++)
            #pragma unroll
            for (int r = 0; r < 4; r++) acc[i][j][r] = 0.f;

    const int lg  = lane >> 2;
    const int lk4 = (lane & 3) * 4;

    g16_copy(sb0, Ab, Bb, K, 0, tid);
    CP_COMMIT();

    for (int c = 0; c < NC; c++) {
        if (c + 1 < NC) {
            g16_copy(sb0 + ((c + 1) & 1) * GSTAGE, Ab, Bb, K, (c + 1) << 6, tid);
            CP_COMMIT();
            CP_WAIT(1);
        } else {
            CP_WAIT(0);
        }
        __syncthreads();

        const uint32_t sb = sb0 + (c & 1) * GSTAGE;

        #pragma unroll
        for (int ks = 0; ks < 4; ks++) {
            const int kb = ks * 32 + lk4;

            uint32_t ah[4][4], bh[4][2];
            #pragma unroll
            for (int mt = 0; mt < 4; mt++) {
                int r0 = warp_m + mt * 16 + lg;
                int r1 = r0 + 8;
                uint32_t rb0 = r0 * 128, rx0 = (r0 & 7) << 4;
                uint32_t rb1 = r1 * 128, rx1 = (r1 & 7) << 4;
                ah[mt][0] = lds32(sb + rb0 + (kb ^ rx0));
                ah[mt][1] = lds32(sb + rb1 + (kb ^ rx1));
                ah[mt][2] = lds32(sb + rb0 + ((kb + 16) ^ rx0));
                ah[mt][3] = lds32(sb + rb1 + ((kb + 16) ^ rx1));
            }
            #pragma unroll
            for (int nt = 0; nt < 4; nt++) {
                int n = warp_n + nt * 8 + lg;
                uint32_t rb = n * 128, rx = (n & 7) << 4;
                bh[nt][0] = lds32(sb + GT_BYTES + rb + (kb ^ rx));
                bh[nt][1] = lds32(sb + GT_BYTES + rb + ((kb + 16) ^ rx));
            }
            #pragma unroll
            for (int mt = 0; mt < 4; mt++)
                #pragma unroll
                for (int nt = 0; nt < 4; nt++)
                    MMA_F16(acc[mt][nt], ah[mt], bh[nt][0], bh[nt][1]);
        }
        __syncthreads();
    }

    #pragma unroll
    for (int mt = 0; mt < 4; mt++) {
        int row = bm + warp_m + mt * 16 + lg;
        #pragma unroll
        for (int nt = 0; nt < 4; nt++) {
            int col = bn + warp_n + nt * 8 + (lane & 3) * 2;
            *(float2*)(C + (size_t)row * N + col) =
                make_float2(acc[mt][nt][0], acc[mt][nt][1]);
            *(float2*)(C + (size_t)(row + 8) * N + col) =
                make_float2(acc[mt][nt][2], acc[mt][nt][3]);
        }
    }
}

// ---------------------------------------------------------------------------
// Flash attention v14: K-tile 128, QK^T fp16 single-pass, PV fp16 SINGLE-PASS
// (P and V each rn-rounded fp16; weighted-average error ~1.4e-4 rel, no sqrt-N
// growth). Deferred l-sum, fp16 epilogue.
// Smem: Q 32KB + 2 stages x (K 32 + V 32) = 160KB.
// ---------------------------------------------------------------------------
#define FQ14 (128 * 256)              // Q fp16
#define FK14 (128 * 256)              // K fp16 (128 keys)
#define FV14 (128 * 256)              // V fp16
#define FST14 (FK14 + FV14)           // 64KB per stage
#define FA14_SMEM (FQ14 + 2 * FST14)  // 163840

__device__ __forceinline__ void fa14_load_kv(
    uint32_t sbase, const __half* __restrict__ K16,
    const __half* __restrict__ V16, int tk0, int g, int tid)
{
    const __half* srcs[2] = {K16 + (size_t)tk0 * (KV_*HD_) + g * HD_,
                             V16 + (size_t)tk0 * (KV_*HD_) + g * HD_};
    #pragma unroll
    for (int t = 0; t < 2; t++) {
        #pragma unroll
        for (int it = 0; it < 8; it++) {
            int idx = it * 256 + tid;
            int row = idx >> 4, ch = idx & 15;
            uint32_t dst = sbase + t * FK14 + row * 256 +
                           (uint32_t)((ch * 16) ^ ((row & 7) << 4));
            cp_async16(dst, srcs[t] + (size_t)row * (KV_*HD_) + ch * 8);
        }
    }
}

__global__ void __launch_bounds__(256, 1)
flash_v14(const __half* __restrict__ Q16, const __half* __restrict__ K16,
          const __half* __restrict__ V16, __half* __restrict__ Og)
{
    extern __shared__ __align__(1024) char fsm[];
    const uint32_t sb = smem_to_u32(fsm);
    const int tid  = threadIdx.x;
    const int wid  = tid >> 5;
    const int lane = tid & 31;
    const int qt = (gridDim.x - 1) - blockIdx.x;   // heavy tiles first
    const int h  = blockIdx.y;
    const int b  = blockIdx.z;
    const int g  = h / REP_;
    const int q0 = qt * 128;
    const int t0 = b * S_ + q0;
    const int nt = qt + 1;                         // 128-key tiles

    const int l7    = lane & 7;
    const int lb8   = (lane >> 3) & 1;
    const int lhi16 = (lane >= 16) ? 16 : 0;
    const int qrow  = 16 * wid + l7 + lb8 * 8;
    const uint32_t qswz = (uint32_t)(l7 << 4);
    const int krow_l = l7 + ((lane >= 16) ? 8 : 0);
    const int kgsel  = lb8 * 16;
    const uint32_t kswz = (uint32_t)(l7 << 4);
    const int vrow_l = l7 + lb8 * 8;
    const int vgsel  = lhi16;
    const uint32_t vswz = (uint32_t)(l7 << 4);

    fa14_load_kv(sb + FQ14, K16, V16, b * S_, g, tid);
    CP_COMMIT();
    {   // stage Q (fp16, 128 rows x 256B)
        const __half* src = Q16 + (size_t)t0 * D_ + h * HD_;
        #pragma unroll
        for (int it = 0; it < 8; it++) {
            int idx = it * 256 + tid;
            int row = idx >> 4, ch = idx & 15;
            uint32_t dst = sb + row * 256 + (uint32_t)((ch * 16) ^ ((row & 7) << 4));
            cp_async16(dst, src + (size_t)row * D_ + ch * 8);
        }
        CP_COMMIT();
    }

    float o[16][4];
    #pragma unroll
    for (int f = 0; f < 16; f++)
        #pragma unroll
        for (int r = 0; r < 4; r++) o[f][r] = 0.f;
    float m0 = -1e30f, m1 = -1e30f;
    float lsum0 = 0.f, lsum1 = 0.f;

    const int r0g = q0 + 16 * wid + (lane >> 2);
    const int c0l = (lane & 3) * 2;

    for (int t = 0; t < nt; t++) {
        CP_WAIT(0);
        __syncthreads();
        if (t + 1 < nt) {
            fa14_load_kv(sb + FQ14 + ((t + 1) & 1) * FST14,
                         K16, V16, b * S_ + (t + 1) * 128, g, tid);
            CP_COMMIT();
        }

        const uint32_t kb  = sb + FQ14 + (t & 1) * FST14;
        const uint32_t vb  = kb + FK14;

        float s[16][4];
        #pragma unroll
        for (int j = 0; j < 16; j++)
            #pragma unroll
            for (int r = 0; r < 4; r++) s[j][r] = 0.f;

        // ---- S = Q K^T (fp16 single pass, 128 keys) ----
        #pragma unroll
        for (int kk = 0; kk < 8; kk++) {
            uint32_t qh[4];
            uint32_t qa = sb + qrow * 256 + (uint32_t)(((kk * 32) + lhi16) ^ qswz);
            LDSM4(qh[0], qh[1], qh[2], qh[3], qa);
            #pragma unroll
            for (int np = 0; np < 8; np++) {
                uint32_t ka = kb + (np * 16 + krow_l) * 256 +
                              (uint32_t)(((kk * 32) + kgsel) ^ kswz);
                uint32_t b0, b1, b2, b3;
                LDSM4(b0, b1, b2, b3, ka);
                MMA_F16(s[2*np],   qh, b0, b1);
                MMA_F16(s[2*np+1], qh, b2, b3);
            }
        }

        if (t == qt) {   // diagonal tile: causal mask
            const int k0 = t * 128;
            #pragma unroll
            for (int j = 0; j < 16; j++) {
                int cg = k0 + 8 * j + c0l;
                if (cg     > r0g)     s[j][0] = -1e30f;
                if (cg + 1 > r0g)     s[j][1] = -1e30f;
                if (cg     > r0g + 8) s[j][2] = -1e30f;
                if (cg + 1 > r0g + 8) s[j][3] = -1e30f;
            }
        }

        // ---- online softmax ----
        float rm0 = -1e30f, rm1 = -1e30f;
        #pragma unroll
        for (int j = 0; j < 16; j++) {
            rm0 = fmaxf(rm0, fmaxf(s[j][0], s[j][1]));
            rm1 = fmaxf(rm1, fmaxf(s[j][2], s[j][3]));
        }
        rm0 = fmaxf(rm0, __shfl_xor_sync(0xffffffffu, rm0, 1));
        rm0 = fmaxf(rm0, __shfl_xor_sync(0xffffffffu, rm0, 2));
        rm1 = fmaxf(rm1, __shfl_xor_sync(0xffffffffu, rm1, 1));
        rm1 = fmaxf(rm1, __shfl_xor_sync(0xffffffffu, rm1, 2));
        float mn0 = fmaxf(m0, rm0), mn1 = fmaxf(m1, rm1);
        float a0 = __expf(m0 - mn0), a1 = __expf(m1 - mn1);
        m0 = mn0; m1 = mn1;
        float sum0 = 0.f, sum1 = 0.f;
        #pragma unroll
        for (int j = 0; j < 16; j++) {
            s[j][0] = __expf(s[j][0] - mn0);
            s[j][1] = __expf(s[j][1] - mn0);
            s[j][2] = __expf(s[j][2] - mn1);
            s[j][3] = __expf(s[j][3] - mn1);
            sum0 += s[j][0] + s[j][1];
            sum1 += s[j][2] + s[j][3];
        }
        lsum0 = lsum0 * a0 + sum0;
        lsum1 = lsum1 * a1 + sum1;
        #pragma unroll
        for (int f = 0; f < 16; f++) {
            o[f][0] *= a0; o[f][1] *= a0;
            o[f][2] *= a1; o[f][3] *= a1;
        }

        // ---- O += P V (fp16 single pass) ----
        #pragma unroll
        for (int kk = 0; kk < 8; kk++) {
            uint32_t ah[4];
            ah[0] = packf16(s[2*kk][0],   s[2*kk][1]);
            ah[1] = packf16(s[2*kk][2],   s[2*kk][3]);
            ah[2] = packf16(s[2*kk+1][0], s[2*kk+1][1]);
            ah[3] = packf16(s[2*kk+1][2], s[2*kk+1][3]);
            #pragma unroll
            for (int dgp = 0; dgp < 8; dgp++) {
                uint32_t va = vb + (kk * 16 + vrow_l) * 256 +
                              (uint32_t)(((dgp * 32) + vgsel) ^ vswz);
                uint32_t b0, b1, b2, b3;
                LDSM4T(b0, b1, b2, b3, va);
                MMA_F16(o[2*dgp],   ah, b0, b1);
                MMA_F16(o[2*dgp+1], ah, b2, b3);
            }
        }
    }

    // epilogue: reduce l once, normalize, write fp16 (feeds fp16 O-proj)
    lsum0 += __shfl_xor_sync(0xffffffffu, lsum0, 1);
    lsum0 += __shfl_xor_sync(0xffffffffu, lsum0, 2);
    lsum1 += __shfl_xor_sync(0xffffffffu, lsum1, 1);
    lsum1 += __shfl_xor_sync(0xffffffffu, lsum1, 2);
    const float inv0 = 1.0f / lsum0;
    const float inv1 = 1.0f / lsum1;
    const int rowg = t0 + 16 * wid + (lane >> 2);
    #pragma unroll
    for (int dg = 0; dg < 16; dg++) {
        int col = h * HD_ + dg * 8 + (lane & 3) * 2;
        *reinterpret_cast<uint32_t*>(Og + (size_t)rowg * D_ + col) =
            packf16(o[dg][0] * inv0, o[dg][1] * inv0);
        *reinterpret_cast<uint32_t*>(Og + (size_t)(rowg + 8) * D_ + col) =
            packf16(o[dg][2] * inv1, o[dg][3] * inv1);
    }
}

// ---------------------------------------------------------------------------
extern "C" void kernel_launch(void* const* d_in, const int* in_sizes, int n_in,
                              void* d_out, int out_size)
{
    const float* x  = (const float*)d_in[0];
    const float* fc = (const float*)d_in[1];
    const float* fs = (const float*)d_in[2];
    const float* wq = (const float*)d_in[3];
    const float* wk = (const float*)d_in[4];
    const float* wv = (const float*)d_in[5];
    const float* wo = (const float*)d_in[6];
    float* out = (float*)d_out;

    float *qp, *kp, *vp;
    cudaGetSymbolAddress((void**)&qp, g_q);
    cudaGetSymbolAddress((void**)&kp, g_k);
    cudaGetSymbolAddress((void**)&vp, g_v);
    __half *x16, *wq16, *wk16, *wv16, *wo16, *attn16, *q16, *k16, *v16;
    cudaGetSymbolAddress((void**)&x16,  g_x16);
    cudaGetSymbolAddress((void**)&wq16, g_wq16);
    cudaGetSymbolAddress((void**)&wk16, g_wk16);
    cudaGetSymbolAddress((void**)&wv16, g_wv16);
    cudaGetSymbolAddress((void**)&wo16, g_wo16);
    cudaGetSymbolAddress((void**)&attn16, g_attn16);
    cudaGetSymbolAddress((void**)&q16, g_q16);
    cudaGetSymbolAddress((void**)&k16, g_k16);
    cudaGetSymbolAddress((void**)&v16, g_v16);

    cudaFuncSetAttribute(gemm_f16,
                         cudaFuncAttributeMaxDynamicSharedMemorySize, GF16_SMEM);
    cudaFuncSetAttribute(flash_v14,
                         cudaFuncAttributeMaxDynamicSharedMemorySize, FA14_SMEM);

    const int n4_xd = T_ * D_ / 4;
    const int n4_w  = D_ * D_ / 4;
    const int n4_kv = KV_ * HD_ * D_ / 4;
    const int n4_kvt = T_ * KV_ * HD_ / 4;
    const float scale = 0.08838834764831845f;  // 1/sqrt(128)

    to_f16<<<(n4_xd + 255)/256, 256>>>(x,  x16,  n4_xd);
    to_f16<<<(n4_w  + 255)/256, 256>>>(wq, wq16, n4_w);
    to_f16<<<(n4_kv + 255)/256, 256>>>(wk, wk16, n4_kv);
    to_f16<<<(n4_kv + 255)/256, 256>>>(wv, wv16, n4_kv);
    to_f16<<<(n4_w  + 255)/256, 256>>>(wo, wo16, n4_w);

    dim3 blk(256);
    // Q projection
    gemm_f16<<<dim3(D_/128, T_/128, 1), blk, GF16_SMEM>>>(
        x16, wq16, wq16, qp, qp, D_, D_);
    // fused K+V projections (z selects weight/output)
    gemm_f16<<<dim3((KV_*HD_)/128, T_/128, 2), blk, GF16_SMEM>>>(
        x16, wk16, wv16, kp, vp, KV_*HD_, D_);

    rope_f16<<<(T_*H_*(HD_/4))/256,  256>>>(qp, q16, fc, fs, H_, scale);
    rope_f16<<<(T_*KV_*(HD_/4))/256, 256>>>(kp, k16, fc, fs, KV_, 1.0f);
    to_f16<<<(n4_kvt + 255)/256, 256>>>(vp, v16, n4_kvt);

    flash_v14<<<dim3(S_/128, H_, B_), blk, FA14_SMEM>>>(q16, k16, v16, attn16);

    // O projection
    gemm_f16<<<dim3(D_/128, T_/128, 1), blk, GF16_SMEM>>>(
        attn16, wo16, wo16, out, out, D_, D_);
}

// round 15
// speedup vs baseline: 2.8383x; 1.0046x over previous
#include <cuda_runtime.h>
#include <cuda_bf16.h>
#include <cuda_fp16.h>
#include <math.h>
#include <cstdint>

#define B_ 2
#define S_ 2048
#define D_ 4096
#define H_ 32
#define KV_ 8
#define HD_ 128
#define T_ (B_*S_)
#define REP_ (H_/KV_)

// ---------------------------------------------------------------------------
// Scratch (device globals: allocation-free rule)
// ---------------------------------------------------------------------------
__device__ float g_q[T_ * D_];             // Q proj (pre-rope fp32)
__device__ float g_k[T_ * KV_ * HD_];      // K proj (pre-rope fp32)
__device__ float g_v[T_ * KV_ * HD_];      // V proj fp32
__device__ __half g_attn16[T_ * D_];       // attention out (fp16, feeds O-proj)

__device__ __half g_x16[T_ * D_];          // fp16 GEMM operands
__device__ __half g_wq16[D_ * D_];
__device__ __half g_wk16[KV_ * HD_ * D_];
__device__ __half g_wv16[KV_ * HD_ * D_];
__device__ __half g_wo16[D_ * D_];

__device__ __half g_q16[T_ * D_];          // roped + scale*log2e fp16 Q
__device__ __half g_k16[T_ * KV_ * HD_];   // roped fp16 K
__device__ __half g_v16[T_ * KV_ * HD_];   // V fp16

// ---------------------------------------------------------------------------
// Helpers
// ---------------------------------------------------------------------------
__device__ __forceinline__ uint32_t smem_to_u32(const void* smem_ptr) {
    uint32_t addr;
    asm("{ .reg .u64 tmp; cvta.to.shared.u64 tmp, %1; cvt.u32.u64 %0, tmp; }"
        : "=r"(addr) : "l"(smem_ptr));
    return addr;
}
__device__ __forceinline__ void cp_async16(uint32_t saddr, const void* gaddr) {
    asm volatile("cp.async.cg.shared.global [%0], [%1], 16;"
                 :: "r"(saddr), "l"(gaddr));
}
#define CP_COMMIT() asm volatile("cp.async.commit_group;")
#define CP_WAIT(n)  asm volatile("cp.async.wait_group %0;" :: "n"(n))

__device__ __forceinline__ uint32_t lds32(uint32_t addr) {
    uint32_t v;
    asm("ld.shared.b32 %0, [%1];" : "=r"(v) : "r"(addr));
    return v;
}

#define MMA_F16(d, a, bb0, bb1) \
    asm volatile("mma.sync.aligned.m16n8k16.row.col.f32.f16.f16.f32 " \
        "{%0,%1,%2,%3}, {%4,%5,%6,%7}, {%8,%9}, {%0,%1,%2,%3};" \
        : "+f"((d)[0]), "+f"((d)[1]), "+f"((d)[2]), "+f"((d)[3]) \
        : "r"((a)[0]), "r"((a)[1]), "r"((a)[2]), "r"((a)[3]), \
          "r"(bb0), "r"(bb1))

#define LDSM4(d0,d1,d2,d3,a) \
    asm volatile("ldmatrix.sync.aligned.m8n8.x4.shared.b16 {%0,%1,%2,%3}, [%4];" \
        : "=r"(d0), "=r"(d1), "=r"(d2), "=r"(d3) : "r"(a))
#define LDSM4T(d0,d1,d2,d3,a) \
    asm volatile("ldmatrix.sync.aligned.m8n8.x4.trans.shared.b16 {%0,%1,%2,%3}, [%4];" \
        : "=r"(d0), "=r"(d1), "=r"(d2), "=r"(d3) : "r"(a))

__device__ __forceinline__ uint32_t packf16(float lo, float hi) {
    uint32_t r;
    asm("cvt.rn.f16x2.f32 %0, %1, %2;" : "=r"(r) : "f"(hi), "f"(lo));
    return r;
}
__device__ __forceinline__ float ex2f(float x) {
    float r;
    asm("ex2.approx.f32 %0, %1;" : "=f"(r) : "f"(x));
    return r;
}
__device__ __forceinline__ uint32_t ex2h2(uint32_t x) {
    uint32_t r;
    asm("ex2.approx.f16x2 %0, %1;" : "=r"(r) : "r"(x));
    return r;
}

// ---------------------------------------------------------------------------
// fp32 -> fp16 convert
// ---------------------------------------------------------------------------
__global__ void to_f16(const float* __restrict__ X, __half* __restrict__ Y, int n4)
{
    int i = blockIdx.x * blockDim.x + threadIdx.x;
    if (i >= n4) return;
    float4 v = reinterpret_cast<const float4*>(X)[i];
    uint2 o;
    o.x = packf16(v.x, v.y);
    o.y = packf16(v.z, v.w);
    reinterpret_cast<uint2*>(Y)[i] = o;
}

// ---------------------------------------------------------------------------
// Fused RoPE (+scale) + fp16 convert (flash QK operands)
// ---------------------------------------------------------------------------
__global__ void rope_f16(const float* __restrict__ src, __half* __restrict__ dst,
                         const float* __restrict__ fc, const float* __restrict__ fs,
                         int heads, float sc)
{
    int idx = blockIdx.x * blockDim.x + threadIdx.x;
    int total = T_ * heads * (HD_/4);
    if (idx >= total) return;
    int i32 = idx & 31;
    int rem = idx >> 5;
    int h   = rem % heads;
    int t   = rem / heads;
    int s   = t & (S_ - 1);
    int p0  = 2 * i32;
    float c0 = fc[s*64 + p0],     s0 = fs[s*64 + p0];
    float c1 = fc[s*64 + p0 + 1], s1 = fs[s*64 + p0 + 1];
    size_t base = (size_t)t * heads * HD_ + h * HD_ + 4*i32;
    float4 v = *reinterpret_cast<const float4*>(src + base);
    uint2 o;
    o.x = packf16((v.x * c0 - v.y * s0) * sc, (v.x * s0 + v.y * c0) * sc);
    o.y = packf16((v.z * c1 - v.w * s1) * sc, (v.z * s1 + v.w * c1) * sc);
    *reinterpret_cast<uint2*>(dst + base) = o;
}

// ---------------------------------------------------------------------------
// fp16 single-pass GEMM (R11-winning body) + blockIdx.z weight/output select
// ---------------------------------------------------------------------------
#define GT_BYTES 16384
#define GSTAGE (2 * GT_BYTES)
#define GF16_SMEM (2 * GSTAGE)

__device__ __forceinline__ void g16_copy(
    uint32_t sbase, const __half* __restrict__ Ab, const __half* __restrict__ Bb,
    int K, int k0, int tid)
{
    #pragma unroll
    for (int t = 0; t < 2; t++) {
        const __half* src = t ? Bb : Ab;
        uint32_t toff = sbase + t * GT_BYTES;
        #pragma unroll
        for (int p = 0; p < 4; p++) {
            int idx = p * 256 + tid;
            int row = idx >> 3;
            int ch  = idx & 7;
            uint32_t dst = toff + row * 128 +
                           (uint32_t)((ch * 16) ^ ((row & 7) << 4));
            cp_async16(dst, src + (size_t)row * K + k0 + ch * 8);
        }
    }
}

__global__ void __launch_bounds__(256)
gemm_f16(const __half* __restrict__ A,
         const __half* __restrict__ B0, const __half* __restrict__ B1,
         float* __restrict__ C0, float* __restrict__ C1,
         int N, int K)
{
    extern __shared__ __align__(1024) char smem[];
    const uint32_t sb0 = smem_to_u32(smem);
    const int tid  = threadIdx.x;
    const int wid  = tid >> 5;
    const int lane = tid & 31;
    const int bm = blockIdx.y * 128;
    const int bn = blockIdx.x * 128;
    const __half* Bw = blockIdx.z ? B1 : B0;
    float* C = blockIdx.z ? C1 : C0;
    const int warp_m = (wid >> 2) * 64;
    const int warp_n = (wid & 3) * 32;
    const int NC = K >> 6;

    const __half* Ab = A  + (size_t)bm * K;
    const __half* Bb = Bw + (size_t)bn * K;

    float acc[4][4][4];
    #pragma unroll
    for (int i = 0; i < 4; i++)
        #pragma unroll
        for (int j = 0; j < 4; j++)
            #pragma unroll
            for (int r = 0; r < 4; r++) acc[i][j][r] = 0.f;

    const int lg  = lane >> 2;
    const int lk4 = (lane & 3) * 4;

    g16_copy(sb0, Ab, Bb, K, 0, tid);
    CP_COMMIT();

    for (int c = 0; c < NC; c++) {
        if (c + 1 < NC) {
            g16_copy(sb0 + ((c + 1) & 1) * GSTAGE, Ab, Bb, K, (c + 1) << 6, tid);
            CP_COMMIT();
            CP_WAIT(1);
        } else {
            CP_WAIT(0);
        }
        __syncthreads();

        const uint32_t sb = sb0 + (c & 1) * GSTAGE;

        #pragma unroll
        for (int ks = 0; ks < 4; ks++) {
            const int kb = ks * 32 + lk4;

            uint32_t ah[4][4], bh[4][2];
            #pragma unroll
            for (int mt = 0; mt < 4; mt++) {
                int r0 = warp_m + mt * 16 + lg;
                int r1 = r0 + 8;
                uint32_t rb0 = r0 * 128, rx0 = (r0 & 7) << 4;
                uint32_t rb1 = r1 * 128, rx1 = (r1 & 7) << 4;
                ah[mt][0] = lds32(sb + rb0 + (kb ^ rx0));
                ah[mt][1] = lds32(sb + rb1 + (kb ^ rx1));
                ah[mt][2] = lds32(sb + rb0 + ((kb + 16) ^ rx0));
                ah[mt][3] = lds32(sb + rb1 + ((kb + 16) ^ rx1));
            }
            #pragma unroll
            for (int nt = 0; nt < 4; nt++) {
                int n = warp_n + nt * 8 + lg;
                uint32_t rb = n * 128, rx = (n & 7) << 4;
                bh[nt][0] = lds32(sb + GT_BYTES + rb + (kb ^ rx));
                bh[nt][1] = lds32(sb + GT_BYTES + rb + ((kb + 16) ^ rx));
            }
            #pragma unroll
            for (int mt = 0; mt < 4; mt++)
                #pragma unroll
                for (int nt = 0; nt < 4; nt++)
                    MMA_F16(acc[mt][nt], ah[mt], bh[nt][0], bh[nt][1]);
        }
        __syncthreads();
    }

    #pragma unroll
    for (int mt = 0; mt < 4; mt++) {
        int row = bm + warp_m + mt * 16 + lg;
        #pragma unroll
        for (int nt = 0; nt < 4; nt++) {
            int col = bn + warp_n + nt * 8 + (lane & 3) * 2;
            *(float2*)(C + (size_t)row * N + col) =
                make_float2(acc[mt][nt][0], acc[mt][nt][1]);
            *(float2*)(C + (size_t)(row + 8) * N + col) =
                make_float2(acc[mt][nt][2], acc[mt][nt][3]);
        }
    }
}

// ---------------------------------------------------------------------------
// Flash attention v15: log2-domain softmax with ex2.approx.f16x2 (1 MUFU per
// 2 elements, output IS the fp16 P fragment), l-sum via ones-B MMA (exact,
// consistent with PV numerator, no epilogue reduce). K-tile 128, QK fp16,
// PV fp16 single-pass.
// ---------------------------------------------------------------------------
#define FQ14 (128 * 256)              // Q fp16
#define FK14 (128 * 256)              // K fp16 (128 keys)
#define FV14 (128 * 256)              // V fp16
#define FST14 (FK14 + FV14)           // 64KB per stage
#define FA14_SMEM (FQ14 + 2 * FST14)  // 163840

__device__ __forceinline__ void fa14_load_kv(
    uint32_t sbase, const __half* __restrict__ K16,
    const __half* __restrict__ V16, int tk0, int g, int tid)
{
    const __half* srcs[2] = {K16 + (size_t)tk0 * (KV_*HD_) + g * HD_,
                             V16 + (size_t)tk0 * (KV_*HD_) + g * HD_};
    #pragma unroll
    for (int t = 0; t < 2; t++) {
        #pragma unroll
        for (int it = 0; it < 8; it++) {
            int idx = it * 256 + tid;
            int row = idx >> 4, ch = idx & 15;
            uint32_t dst = sbase + t * FK14 + row * 256 +
                           (uint32_t)((ch * 16) ^ ((row & 7) << 4));
            cp_async16(dst, srcs[t] + (size_t)row * (KV_*HD_) + ch * 8);
        }
    }
}

__global__ void __launch_bounds__(256, 1)
flash_v15(const __half* __restrict__ Q16, const __half* __restrict__ K16,
          const __half* __restrict__ V16, __half* __restrict__ Og)
{
    extern __shared__ __align__(1024) char fsm[];
    const uint32_t sb = smem_to_u32(fsm);
    const int tid  = threadIdx.x;
    const int wid  = tid >> 5;
    const int lane = tid & 31;
    const int qt = (gridDim.x - 1) - blockIdx.x;   // heavy tiles first
    const int h  = blockIdx.y;
    const int b  = blockIdx.z;
    const int g  = h / REP_;
    const int q0 = qt * 128;
    const int t0 = b * S_ + q0;
    const int nt = qt + 1;                         // 128-key tiles

    const int l7    = lane & 7;
    const int lb8   = (lane >> 3) & 1;
    const int lhi16 = (lane >= 16) ? 16 : 0;
    const int qrow  = 16 * wid + l7 + lb8 * 8;
    const uint32_t qswz = (uint32_t)(l7 << 4);
    const int krow_l = l7 + ((lane >= 16) ? 8 : 0);
    const int kgsel  = lb8 * 16;
    const uint32_t kswz = (uint32_t)(l7 << 4);
    const int vrow_l = l7 + lb8 * 8;
    const int vgsel  = lhi16;
    const uint32_t vswz = (uint32_t)(l7 << 4);
    const uint32_t ONESH2 = 0x3C003C00u;           // (1.0h, 1.0h)

    fa14_load_kv(sb + FQ14, K16, V16, b * S_, g, tid);
    CP_COMMIT();
    {   // stage Q (fp16, 128 rows x 256B)
        const __half* src = Q16 + (size_t)t0 * D_ + h * HD_;
        #pragma unroll
        for (int it = 0; it < 8; it++) {
            int idx = it * 256 + tid;
            int row = idx >> 4, ch = idx & 15;
            uint32_t dst = sb + row * 256 + (uint32_t)((ch * 16) ^ ((row & 7) << 4));
            cp_async16(dst, src + (size_t)row * D_ + ch * 8);
        }
        CP_COMMIT();
    }

    float o[16][4];
    #pragma unroll
    for (int f = 0; f < 16; f++)
        #pragma unroll
        for (int r = 0; r < 4; r++) o[f][r] = 0.f;
    float m0 = -1e30f, m1 = -1e30f;
    float lsum0 = 0.f, lsum1 = 0.f;   // FULL row sums (ones-MMA), no reduce

    const int r0g = q0 + 16 * wid + (lane >> 2);
    const int c0l = (lane & 3) * 2;

    for (int t = 0; t < nt; t++) {
        CP_WAIT(0);
        __syncthreads();
        if (t + 1 < nt) {
            fa14_load_kv(sb + FQ14 + ((t + 1) & 1) * FST14,
                         K16, V16, b * S_ + (t + 1) * 128, g, tid);
            CP_COMMIT();
        }

        const uint32_t kb  = sb + FQ14 + (t & 1) * FST14;
        const uint32_t vb  = kb + FK14;

        float s[16][4];
        #pragma unroll
        for (int j = 0; j < 16; j++)
            #pragma unroll
            for (int r = 0; r < 4; r++) s[j][r] = 0.f;

        // ---- S = Q K^T (fp16 single pass; log2-domain scores) ----
        #pragma unroll
        for (int kk = 0; kk < 8; kk++) {
            uint32_t qh[4];
            uint32_t qa = sb + qrow * 256 + (uint32_t)(((kk * 32) + lhi16) ^ qswz);
            LDSM4(qh[0], qh[1], qh[2], qh[3], qa);
            #pragma unroll
            for (int np = 0; np < 8; np++) {
                uint32_t ka = kb + (np * 16 + krow_l) * 256 +
                              (uint32_t)(((kk * 32) + kgsel) ^ kswz);
                uint32_t b0, b1, b2, b3;
                LDSM4(b0, b1, b2, b3, ka);
                MMA_F16(s[2*np],   qh, b0, b1);
                MMA_F16(s[2*np+1], qh, b2, b3);
            }
        }

        if (t == qt) {   // diagonal tile: causal mask
            const int k0 = t * 128;
            #pragma unroll
            for (int j = 0; j < 16; j++) {
                int cg = k0 + 8 * j + c0l;
                if (cg     > r0g)     s[j][0] = -1e30f;
                if (cg + 1 > r0g)     s[j][1] = -1e30f;
                if (cg     > r0g + 8) s[j][2] = -1e30f;
                if (cg + 1 > r0g + 8) s[j][3] = -1e30f;
            }
        }

        // ---- online softmax (log2 domain) ----
        float rm0 = -1e30f, rm1 = -1e30f;
        #pragma unroll
        for (int j = 0; j < 16; j++) {
            rm0 = fmaxf(rm0, fmaxf(s[j][0], s[j][1]));
            rm1 = fmaxf(rm1, fmaxf(s[j][2], s[j][3]));
        }
        rm0 = fmaxf(rm0, __shfl_xor_sync(0xffffffffu, rm0, 1));
        rm0 = fmaxf(rm0, __shfl_xor_sync(0xffffffffu, rm0, 2));
        rm1 = fmaxf(rm1, __shfl_xor_sync(0xffffffffu, rm1, 1));
        rm1 = fmaxf(rm1, __shfl_xor_sync(0xffffffffu, rm1, 2));
        float mn0 = fmaxf(m0, rm0), mn1 = fmaxf(m1, rm1);
        float a0 = ex2f(m0 - mn0), a1 = ex2f(m1 - mn1);
        m0 = mn0; m1 = mn1;

        // p = 2^(s-m) via f16x2 MUFU; result doubles as fp16 PV A-fragment.
        // Store packed pairs in s[j][0] (row r) and s[j][1] (row r+8).
        #pragma unroll
        for (int j = 0; j < 16; j++) {
            uint32_t e01 = ex2h2(packf16(s[j][0] - mn0, s[j][1] - mn0));
            uint32_t e23 = ex2h2(packf16(s[j][2] - mn1, s[j][3] - mn1));
            s[j][0] = __uint_as_float(e01);
            s[j][1] = __uint_as_float(e23);
        }

        #pragma unroll
        for (int f = 0; f < 16; f++) {
            o[f][0] *= a0; o[f][1] *= a0;
            o[f][2] *= a1; o[f][3] *= a1;
        }

        // ---- O += P V (fp16) and l += P @ ones (exact row sums) ----
        float lacc[4] = {0.f, 0.f, 0.f, 0.f};
        #pragma unroll
        for (int kk = 0; kk < 8; kk++) {
            uint32_t ah[4];
            ah[0] = __float_as_uint(s[2*kk][0]);
            ah[1] = __float_as_uint(s[2*kk][1]);
            ah[2] = __float_as_uint(s[2*kk+1][0]);
            ah[3] = __float_as_uint(s[2*kk+1][1]);
            MMA_F16(lacc, ah, ONESH2, ONESH2);
            #pragma unroll
            for (int dgp = 0; dgp < 8; dgp++) {
                uint32_t va = vb + (kk * 16 + vrow_l) * 256 +
                              (uint32_t)(((dgp * 32) + vgsel) ^ vswz);
                uint32_t b0, b1, b2, b3;
                LDSM4T(b0, b1, b2, b3, va);
                MMA_F16(o[2*dgp],   ah, b0, b1);
                MMA_F16(o[2*dgp+1], ah, b2, b3);
            }
        }
        lsum0 = lsum0 * a0 + lacc[0];
        lsum1 = lsum1 * a1 + lacc[2];
    }

    // epilogue: lsum is already the full row sum — no reduction needed
    const float inv0 = 1.0f / lsum0;
    const float inv1 = 1.0f / lsum1;
    const int rowg = t0 + 16 * wid + (lane >> 2);
    #pragma unroll
    for (int dg = 0; dg < 16; dg++) {
        int col = h * HD_ + dg * 8 + (lane & 3) * 2;
        *reinterpret_cast<uint32_t*>(Og + (size_t)rowg * D_ + col) =
            packf16(o[dg][0] * inv0, o[dg][1] * inv0);
        *reinterpret_cast<uint32_t*>(Og + (size_t)(rowg + 8) * D_ + col) =
            packf16(o[dg][2] * inv1, o[dg][3] * inv1);
    }
}

// ---------------------------------------------------------------------------
extern "C" void kernel_launch(void* const* d_in, const int* in_sizes, int n_in,
                              void* d_out, int out_size)
{
    const float* x  = (const float*)d_in[0];
    const float* fc = (const float*)d_in[1];
    const float* fs = (const float*)d_in[2];
    const float* wq = (const float*)d_in[3];
    const float* wk = (const float*)d_in[4];
    const float* wv = (const float*)d_in[5];
    const float* wo = (const float*)d_in[6];
    float* out = (float*)d_out;

    float *qp, *kp, *vp;
    cudaGetSymbolAddress((void**)&qp, g_q);
    cudaGetSymbolAddress((void**)&kp, g_k);
    cudaGetSymbolAddress((void**)&vp, g_v);
    __half *x16, *wq16, *wk16, *wv16, *wo16, *attn16, *q16, *k16, *v16;
    cudaGetSymbolAddress((void**)&x16,  g_x16);
    cudaGetSymbolAddress((void**)&wq16, g_wq16);
    cudaGetSymbolAddress((void**)&wk16, g_wk16);
    cudaGetSymbolAddress((void**)&wv16, g_wv16);
    cudaGetSymbolAddress((void**)&wo16, g_wo16);
    cudaGetSymbolAddress((void**)&attn16, g_attn16);
    cudaGetSymbolAddress((void**)&q16, g_q16);
    cudaGetSymbolAddress((void**)&k16, g_k16);
    cudaGetSymbolAddress((void**)&v16, g_v16);

    cudaFuncSetAttribute(gemm_f16,
                         cudaFuncAttributeMaxDynamicSharedMemorySize, GF16_SMEM);
    cudaFuncSetAttribute(flash_v15,
                         cudaFuncAttributeMaxDynamicSharedMemorySize, FA14_SMEM);

    const int n4_xd = T_ * D_ / 4;
    const int n4_w  = D_ * D_ / 4;
    const int n4_kv = KV_ * HD_ * D_ / 4;
    const int n4_kvt = T_ * KV_ * HD_ / 4;
    // 1/sqrt(128) * log2(e): softmax in log2 domain
    const float qscale = 0.08838834764831845f * 1.4426950408889634f;

    to_f16<<<(n4_xd + 255)/256, 256>>>(x,  x16,  n4_xd);
    to_f16<<<(n4_w  + 255)/256, 256>>>(wq, wq16, n4_w);
    to_f16<<<(n4_kv + 255)/256, 256>>>(wk, wk16, n4_kv);
    to_f16<<<(n4_kv + 255)/256, 256>>>(wv, wv16, n4_kv);
    to_f16<<<(n4_w  + 255)/256, 256>>>(wo, wo16, n4_w);

    dim3 blk(256);
    // Q projection
    gemm_f16<<<dim3(D_/128, T_/128, 1), blk, GF16_SMEM>>>(
        x16, wq16, wq16, qp, qp, D_, D_);
    // fused K+V projections (z selects weight/output)
    gemm_f16<<<dim3((KV_*HD_)/128, T_/128, 2), blk, GF16_SMEM>>>(
        x16, wk16, wv16, kp, vp, KV_*HD_, D_);

    rope_f16<<<(T_*H_*(HD_/4))/256,  256>>>(qp, q16, fc, fs, H_, qscale);
    rope_f16<<<(T_*KV_*(HD_/4))/256, 256>>>(kp, k16, fc, fs, KV_, 1.0f);
    to_f16<<<(n4_kvt + 255)/256, 256>>>(vp, v16, n4_kvt);

    flash_v15<<<dim3(S_/128, H_, B_), blk, FA14_SMEM>>>(q16, k16, v16, attn16);

    // O projection
    gemm_f16<<<dim3(D_/128, T_/128, 1), blk, GF16_SMEM>>>(
        attn16, wo16, wo16, out, out, D_, D_);
}